// round 1
// baseline (speedup 1.0000x reference)
#include <cuda_runtime.h>
#include <math.h>
#include <float.h>

// ---------------- problem constants ----------------
#define TT   2048   // tokens (B*S)
#define HD   2048   // hidden dim
#define NHQ  16
#define NHKV 4
#define DH   128
#define NE   16
#define NI   768

// ---------------- device scratch ----------------
__device__ float g_q[TT * NHQ * DH];        // 16MB
__device__ float g_k[TT * NHKV * DH];       // 4MB
__device__ float g_v[TT * NHKV * DH];       // 4MB
__device__ float g_attn[TT * NHQ * DH];     // 16MB
__device__ float g_h[TT * HD];              // 16MB residual after attention
__device__ float g_logits[TT * NE];
__device__ int   g_sel[TT * 2];
__device__ int   g_cnt[NE];
__device__ int   g_off[NE];
__device__ int   g_fill[NE];
__device__ int   g_tok[TT * 2];             // assignment slot -> token
__device__ int   g_slot[TT * 2];            // (token, j) -> slot
__device__ float g_up[TT * 2 * NI];         // 12.6MB
__device__ float g_down[TT * 2 * HD];       // 32MB

// ---------------- generic 128x128x8 SGEMM core ----------------
// 256 threads, each computes an 8x8 micro-tile. A row-major (lda), B row-major (ldb).
template<bool GATHER, bool BIAS, bool SILU, bool RESID>
__device__ __forceinline__ void gemm_core(
    const float* __restrict__ A, int lda, const int* __restrict__ gidx,
    const float* __restrict__ B, int ldb,
    float* __restrict__ C, int ldc,
    const float* __restrict__ bias,
    const float* __restrict__ resid,
    int M, int K, int bm, int bn)
{
    __shared__ float As[8][132];
    __shared__ float Bs[8][132];

    const int tid = threadIdx.x;
    const int tx = tid & 15;
    const int ty = tid >> 4;

    float acc[8][8];
#pragma unroll
    for (int i = 0; i < 8; i++)
#pragma unroll
        for (int j = 0; j < 8; j++) acc[i][j] = 0.f;

    // A loading: each thread one float4 (row = tid/2, k4 = (tid&1)*4)
    const int a_row = tid >> 1;
    const int a_k4  = (tid & 1) * 4;
    const int grow  = bm + a_row;
    const bool rowok = (grow < M);
    const float* Arow = A;
    if (rowok) {
        if (GATHER) Arow = A + (size_t)gidx[grow] * lda;
        else        Arow = A + (size_t)grow * lda;
    }
    // B loading: k = tid/32, n4 = (tid&31)*4
    const int b_k  = tid >> 5;
    const int b_n4 = (tid & 31) * 4;

    for (int k0 = 0; k0 < K; k0 += 8) {
        float4 av = make_float4(0.f, 0.f, 0.f, 0.f);
        if (rowok) av = *(const float4*)(Arow + k0 + a_k4);
        float4 bv = *(const float4*)(B + (size_t)(k0 + b_k) * ldb + bn + b_n4);

        __syncthreads();
        As[a_k4 + 0][a_row] = av.x;
        As[a_k4 + 1][a_row] = av.y;
        As[a_k4 + 2][a_row] = av.z;
        As[a_k4 + 3][a_row] = av.w;
        *(float4*)&Bs[b_k][b_n4] = bv;
        __syncthreads();

#pragma unroll
        for (int k = 0; k < 8; k++) {
            float af[8], bf[8];
            *(float4*)(af)     = *(const float4*)&As[k][ty * 8];
            *(float4*)(af + 4) = *(const float4*)&As[k][ty * 8 + 4];
            *(float4*)(bf)     = *(const float4*)&Bs[k][tx * 8];
            *(float4*)(bf + 4) = *(const float4*)&Bs[k][tx * 8 + 4];
#pragma unroll
            for (int i = 0; i < 8; i++)
#pragma unroll
                for (int j = 0; j < 8; j++)
                    acc[i][j] += af[i] * bf[j];
        }
    }

#pragma unroll
    for (int i = 0; i < 8; i++) {
        int row = bm + ty * 8 + i;
        if (row >= M) continue;
#pragma unroll
        for (int j = 0; j < 8; j++) {
            int col = bn + tx * 8 + j;
            float v = acc[i][j];
            if (BIAS) v += bias[col];
            if (SILU) v = v / (1.f + expf(-v));
            if (RESID) v += resid[(size_t)row * ldc + col];
            C[(size_t)row * ldc + col] = v;
        }
    }
}

__global__ __launch_bounds__(256)
void k_gemm(const float* __restrict__ A, const float* __restrict__ B,
            float* __restrict__ C, int M, int N, int K)
{
    gemm_core<false, false, false, false>(A, K, nullptr, B, N, C, N,
                                          nullptr, nullptr, M, K,
                                          blockIdx.y * 128, blockIdx.x * 128);
}

__global__ __launch_bounds__(256)
void k_gemm_resid(const float* __restrict__ A, const float* __restrict__ B,
                  float* __restrict__ C, const float* __restrict__ resid,
                  int M, int N, int K)
{
    gemm_core<false, false, false, true>(A, K, nullptr, B, N, C, N,
                                         nullptr, resid, M, K,
                                         blockIdx.y * 128, blockIdx.x * 128);
}

__global__ __launch_bounds__(256)
void k_moe_up(const float* __restrict__ h, const float* __restrict__ w_up,
              const float* __restrict__ b_up)
{
    int e = blockIdx.z;
    int cnt = g_cnt[e];
    int off = g_off[e];
    int bm = blockIdx.y * 128;
    if (bm >= cnt) return;
    gemm_core<true, true, true, false>(
        h, HD, g_tok + off,
        w_up + (size_t)e * HD * NI, NI,
        g_up + (size_t)off * NI, NI,
        b_up + (size_t)e * NI, nullptr,
        cnt, HD, bm, blockIdx.x * 128);
}

__global__ __launch_bounds__(256)
void k_moe_down(const float* __restrict__ w_down, const float* __restrict__ b_down)
{
    int e = blockIdx.z;
    int cnt = g_cnt[e];
    int off = g_off[e];
    int bm = blockIdx.y * 128;
    if (bm >= cnt) return;
    gemm_core<false, true, false, false>(
        g_up + (size_t)off * NI, NI, nullptr,
        w_down + (size_t)e * NI * HD, HD,
        g_down + (size_t)off * HD, HD,
        b_down + (size_t)e * HD, nullptr,
        cnt, NI, bm, blockIdx.x * 128);
}

// ---------------- RMSNorm + RoPE on q and k (in place) ----------------
__global__ void k_norm_rope(float* __restrict__ q, float* __restrict__ k,
                            const float* __restrict__ qs, const float* __restrict__ ks)
{
    int t = blockIdx.x;
    int head = blockIdx.y;               // 0..NHQ+NHKV-1
    float* base;
    const float* scale;
    if (head < NHQ) { base = q + ((size_t)t * NHQ + head) * DH; scale = qs; }
    else            { base = k + ((size_t)t * NHKV + (head - NHQ)) * DH; scale = ks; }

    int d = threadIdx.x;                 // 128 threads
    float x = base[d];
    float ss = x * x;
#pragma unroll
    for (int o = 16; o; o >>= 1) ss += __shfl_xor_sync(0xffffffffu, ss, o);
    __shared__ float wsum[4];
    if ((d & 31) == 0) wsum[d >> 5] = ss;
    __syncthreads();
    float var = (wsum[0] + wsum[1] + wsum[2] + wsum[3]) * (1.f / 128.f);
    float inv = rsqrtf(var + 1e-6f);
    float xn = x * inv * scale[d];

    __shared__ float sh[128];
    sh[d] = xn;
    __syncthreads();

    int i = d & 63;
    float inv_freq = 1.f / powf(10000.f, (float)i / 64.f);
    float ang = (float)t * inv_freq;
    float c = cosf(ang), s = sinf(ang);
    float rot = (d < 64) ? -sh[d + 64] : sh[d - 64];
    base[d] = xn * c + rot * s;
}

// ---------------- causal flash attention (GQA 4:1), fp32 ----------------
// grid (32 q-tiles, 16 heads), 256 threads, BM=BN=64, D=128
__global__ __launch_bounds__(256)
void k_attn(const float* __restrict__ q, const float* __restrict__ k,
            const float* __restrict__ v, float* __restrict__ o)
{
    extern __shared__ float sm[];
    float* Qs = sm;                  // transposed [128][64]
    float* Ks = Qs + 128 * 64;       // transposed [128][64]
    float* Vs = Ks + 128 * 64;       // row-major [64][128]
    float* Ps = Vs + 64 * 128;       // padded [64][65]

    const int h  = blockIdx.y;
    const int kh = h >> 2;
    const int q0 = blockIdx.x * 64;
    const int tid = threadIdx.x;
    const int ty = tid >> 3;         // 0..31 -> rows 2*ty, 2*ty+1
    const int tx = tid & 7;          // 0..7
    const int r0 = ty * 2;
    const float scale = 0.08838834764831845f; // 1/sqrt(128)

    // load Q tile transposed
    for (int idx = tid; idx < 2048; idx += 256) {
        int r = idx & 63;
        int d4 = (idx >> 6) << 2;
        float4 val = *(const float4*)(q + (size_t)(q0 + r) * (NHQ * DH) + h * DH + d4);
        Qs[(d4 + 0) * 64 + r] = val.x;
        Qs[(d4 + 1) * 64 + r] = val.y;
        Qs[(d4 + 2) * 64 + r] = val.z;
        Qs[(d4 + 3) * 64 + r] = val.w;
    }

    float m0 = -FLT_MAX, m1 = -FLT_MAX, l0 = 0.f, l1 = 0.f;
    float oa0[16], oa1[16];
#pragma unroll
    for (int j = 0; j < 16; j++) { oa0[j] = 0.f; oa1[j] = 0.f; }

    const int ntiles = blockIdx.x + 1;
    for (int tile = 0; tile < ntiles; ++tile) {
        int k0 = tile * 64;
        // load K transposed
        for (int idx = tid; idx < 2048; idx += 256) {
            int r = idx & 63;
            int d4 = (idx >> 6) << 2;
            float4 val = *(const float4*)(k + (size_t)(k0 + r) * (NHKV * DH) + kh * DH + d4);
            Ks[(d4 + 0) * 64 + r] = val.x;
            Ks[(d4 + 1) * 64 + r] = val.y;
            Ks[(d4 + 2) * 64 + r] = val.z;
            Ks[(d4 + 3) * 64 + r] = val.w;
        }
        // load V row-major (coalesced)
        for (int idx = tid; idx < 2048; idx += 256) {
            int d4 = (idx & 31) * 4;
            int r = idx >> 5;
            float4 val = *(const float4*)(v + (size_t)(k0 + r) * (NHKV * DH) + kh * DH + d4);
            *(float4*)&Vs[r * 128 + d4] = val;
        }
        __syncthreads();

        // S = Q K^T  (2 rows x 8 cols per thread)
        float s0[8], s1[8];
#pragma unroll
        for (int j = 0; j < 8; j++) { s0[j] = 0.f; s1[j] = 0.f; }
#pragma unroll 4
        for (int kk = 0; kk < 128; ++kk) {
            float2 qv = *(const float2*)&Qs[kk * 64 + r0];
            float kf[8];
            *(float4*)(kf)     = *(const float4*)&Ks[kk * 64 + tx * 8];
            *(float4*)(kf + 4) = *(const float4*)&Ks[kk * 64 + tx * 8 + 4];
#pragma unroll
            for (int j = 0; j < 8; j++) {
                s0[j] += qv.x * kf[j];
                s1[j] += qv.y * kf[j];
            }
        }

        // scale + causal mask
        const bool diag = (tile == ntiles - 1);
        int qi0 = q0 + r0, qi1 = q0 + r0 + 1;
#pragma unroll
        for (int j = 0; j < 8; j++) {
            int kj = k0 + tx * 8 + j;
            s0[j] = (diag && kj > qi0) ? -FLT_MAX : s0[j] * scale;
            s1[j] = (diag && kj > qi1) ? -FLT_MAX : s1[j] * scale;
        }

        // row max (reduce over 8-lane tx group)
        float tm0 = s0[0], tm1 = s1[0];
#pragma unroll
        for (int j = 1; j < 8; j++) { tm0 = fmaxf(tm0, s0[j]); tm1 = fmaxf(tm1, s1[j]); }
#pragma unroll
        for (int off = 1; off < 8; off <<= 1) {
            tm0 = fmaxf(tm0, __shfl_xor_sync(0xffffffffu, tm0, off));
            tm1 = fmaxf(tm1, __shfl_xor_sync(0xffffffffu, tm1, off));
        }
        float mn0 = fmaxf(m0, tm0), mn1 = fmaxf(m1, tm1);
        float a0 = expf(m0 - mn0), a1 = expf(m1 - mn1);

        float ps0 = 0.f, ps1 = 0.f;
#pragma unroll
        for (int j = 0; j < 8; j++) {
            s0[j] = expf(s0[j] - mn0);
            s1[j] = expf(s1[j] - mn1);
            ps0 += s0[j];
            ps1 += s1[j];
        }
#pragma unroll
        for (int off = 1; off < 8; off <<= 1) {
            ps0 += __shfl_xor_sync(0xffffffffu, ps0, off);
            ps1 += __shfl_xor_sync(0xffffffffu, ps1, off);
        }
        l0 = l0 * a0 + ps0;
        l1 = l1 * a1 + ps1;
        m0 = mn0; m1 = mn1;

#pragma unroll
        for (int j = 0; j < 16; j++) { oa0[j] *= a0; oa1[j] *= a1; }

        // write P (padded stride 65)
#pragma unroll
        for (int j = 0; j < 8; j++) {
            Ps[r0 * 65 + tx * 8 + j]       = s0[j];
            Ps[(r0 + 1) * 65 + tx * 8 + j] = s1[j];
        }
        __syncthreads();

        // O += P V   (2 rows x 16 cols per thread)
#pragma unroll 4
        for (int c = 0; c < 64; ++c) {
            float p0 = Ps[r0 * 65 + c];
            float p1 = Ps[r0 * 65 + 65 + c];
            float vf[16];
            *(float4*)(vf)      = *(const float4*)&Vs[c * 128 + tx * 16];
            *(float4*)(vf + 4)  = *(const float4*)&Vs[c * 128 + tx * 16 + 4];
            *(float4*)(vf + 8)  = *(const float4*)&Vs[c * 128 + tx * 16 + 8];
            *(float4*)(vf + 12) = *(const float4*)&Vs[c * 128 + tx * 16 + 12];
#pragma unroll
            for (int j = 0; j < 16; j++) {
                oa0[j] += p0 * vf[j];
                oa1[j] += p1 * vf[j];
            }
        }
        __syncthreads();
    }

    float inv0 = 1.f / l0, inv1 = 1.f / l1;
    size_t out0 = (size_t)(q0 + r0) * (NHQ * DH) + h * DH + tx * 16;
    size_t out1 = out0 + (NHQ * DH);
#pragma unroll
    for (int j = 0; j < 16; j++) {
        o[out0 + j] = oa0[j] * inv0;
        o[out1 + j] = oa1[j] * inv1;
    }
}

// ---------------- router: logits = h @ router_w, write logits + output ----------------
__global__ void k_router(const float* __restrict__ h, const float* __restrict__ w,
                         float* __restrict__ logits, float* __restrict__ out2)
{
    int t = blockIdx.x * 8 + (threadIdx.x >> 5);
    int lane = threadIdx.x & 31;
    const float* xr = h + (size_t)t * HD;
    float acc[NE];
#pragma unroll
    for (int e = 0; e < NE; e++) acc[e] = 0.f;
    for (int hh = lane; hh < HD; hh += 32) {
        float xv = xr[hh];
        const float* wr = w + hh * NE;
#pragma unroll
        for (int e = 0; e < NE; e++) acc[e] += xv * wr[e];
    }
#pragma unroll
    for (int e = 0; e < NE; e++)
#pragma unroll
        for (int o = 16; o; o >>= 1) acc[e] += __shfl_xor_sync(0xffffffffu, acc[e], o);
    if (lane == 0) {
#pragma unroll
        for (int e = 0; e < NE; e++) {
            logits[t * NE + e] = acc[e];
            out2[t * NE + e] = acc[e];
        }
    }
}

__global__ void k_zero_cnt()
{
    if (threadIdx.x < NE) g_cnt[threadIdx.x] = 0;
}

__global__ void k_top2(const float* __restrict__ logits)
{
    int t = blockIdx.x * 256 + threadIdx.x;
    if (t >= TT) return;
    const float* l = logits + t * NE;
    int i0 = 0; float v0 = l[0];
#pragma unroll
    for (int e = 1; e < NE; e++) { float v = l[e]; if (v > v0) { v0 = v; i0 = e; } }
    int i1 = -1; float v1 = -FLT_MAX;
#pragma unroll
    for (int e = 0; e < NE; e++) {
        if (e == i0) continue;
        float v = l[e];
        if (v > v1) { v1 = v; i1 = e; }
    }
    g_sel[t * 2] = i0;
    g_sel[t * 2 + 1] = i1;
    atomicAdd(&g_cnt[i0], 1);
    atomicAdd(&g_cnt[i1], 1);
}

__global__ void k_offsets()
{
    int s = 0;
    for (int e = 0; e < NE; e++) { g_off[e] = s; s += g_cnt[e]; g_fill[e] = 0; }
}

__global__ void k_fill()
{
    int t = blockIdx.x * 256 + threadIdx.x;
    if (t >= TT) return;
#pragma unroll
    for (int j = 0; j < 2; j++) {
        int e = g_sel[t * 2 + j];
        int pos = atomicAdd(&g_fill[e], 1);
        int slot = g_off[e] + pos;
        g_tok[slot] = t;
        g_slot[t * 2 + j] = slot;
    }
}

__global__ void k_final(float* __restrict__ out)
{
    size_t i = (size_t)blockIdx.x * 256 + threadIdx.x;
    int t = (int)(i >> 11);
    int c = (int)(i & 2047);
    int s0 = g_slot[t * 2];
    int s1 = g_slot[t * 2 + 1];
    out[i] = g_h[i] + g_down[(size_t)s0 * HD + c] + g_down[(size_t)s1 * HD + c];
}

// ---------------- launch ----------------
extern "C" void kernel_launch(void* const* d_in, const int* in_sizes, int n_in,
                              void* d_out, int out_size)
{
    const float* hidden   = (const float*)d_in[0];
    const float* wq       = (const float*)d_in[1];
    const float* wk       = (const float*)d_in[2];
    const float* wv       = (const float*)d_in[3];
    const float* wo       = (const float*)d_in[4];
    const float* q_scale  = (const float*)d_in[5];
    const float* k_scale  = (const float*)d_in[6];
    const float* router_w = (const float*)d_in[7];
    const float* w_up     = (const float*)d_in[8];
    const float* b_up     = (const float*)d_in[9];
    const float* w_down   = (const float*)d_in[10];
    const float* b_down   = (const float*)d_in[11];
    float* out = (float*)d_out;

    float *qb, *kb, *vb, *ab, *hb, *lb;
    cudaGetSymbolAddress((void**)&qb, g_q);
    cudaGetSymbolAddress((void**)&kb, g_k);
    cudaGetSymbolAddress((void**)&vb, g_v);
    cudaGetSymbolAddress((void**)&ab, g_attn);
    cudaGetSymbolAddress((void**)&hb, g_h);
    cudaGetSymbolAddress((void**)&lb, g_logits);

    // QKV projections
    k_gemm<<<dim3(16, 16), 256>>>(hidden, wq, qb, TT, NHQ * DH, HD);
    k_gemm<<<dim3(4, 16), 256>>>(hidden, wk, kb, TT, NHKV * DH, HD);
    k_gemm<<<dim3(4, 16), 256>>>(hidden, wv, vb, TT, NHKV * DH, HD);

    // RMSNorm + RoPE (q and k, in place)
    k_norm_rope<<<dim3(TT, NHQ + NHKV), 128>>>(qb, kb, q_scale, k_scale);

    // flash attention
    const int attn_smem = (128 * 64 + 128 * 64 + 64 * 128 + 64 * 65) * 4;
    cudaFuncSetAttribute(k_attn, cudaFuncAttributeMaxDynamicSharedMemorySize, attn_smem);
    k_attn<<<dim3(32, NHQ), 256, attn_smem>>>(qb, kb, vb, ab);

    // output projection + residual -> h
    k_gemm_resid<<<dim3(16, 16), 256>>>(ab, wo, hb, hidden, TT, HD, HD);

    // router logits (also written to output region 2)
    k_router<<<TT / 8, 256>>>(hb, router_w, lb, out + (size_t)TT * HD);

    // top-2 routing + expert bucketing
    k_zero_cnt<<<1, 32>>>();
    k_top2<<<TT / 256, 256>>>(lb);
    k_offsets<<<1, 1>>>();
    k_fill<<<TT / 256, 256>>>();

    // MoE grouped GEMMs
    k_moe_up<<<dim3(NI / 128, 16, NE), 256>>>(hb, w_up, b_up);
    k_moe_down<<<dim3(HD / 128, 16, NE), 256>>>(w_down, b_down);

    // final: out = h + sum of the two expert contributions
    k_final<<<(TT * HD) / 256, 256>>>(out);
}

// round 2
// speedup vs baseline: 1.6225x; 1.6225x over previous
#include <cuda_runtime.h>
#include <math.h>
#include <float.h>
#include <stdint.h>

// ---------------- problem constants ----------------
#define TT   2048   // tokens (B*S)
#define HD   2048   // hidden dim
#define NHQ  16
#define NHKV 4
#define DH   128
#define NE   16
#define NI   768

// ---------------- device scratch ----------------
__device__ float g_q[TT * NHQ * DH];
__device__ float g_k[TT * NHKV * DH];
__device__ float g_v[TT * NHKV * DH];
__device__ float g_attn[TT * NHQ * DH];
__device__ float g_h[TT * HD];
__device__ float g_logits[TT * NE];
__device__ int   g_sel[TT * 2];
__device__ int   g_cnt[NE];
__device__ int   g_off[NE];
__device__ int   g_fill[NE];
__device__ int   g_tok[TT * 2];
__device__ int   g_slot[TT * 2];
__device__ float g_up[TT * 2 * NI];
__device__ float g_down[TT * 2 * HD];

// ---------------- tf32 helpers ----------------
__device__ __forceinline__ uint32_t f2tf32(float x) {
    uint32_t r;
    asm("cvt.rna.tf32.f32 %0, %1;" : "=r"(r) : "f"(x));
    return r;
}

__device__ __forceinline__ void mma_tf32(float c[4], const uint32_t a[4], const uint32_t b[2]) {
    asm volatile(
        "mma.sync.aligned.m16n8k8.row.col.f32.tf32.tf32.f32 "
        "{%0,%1,%2,%3}, {%4,%5,%6,%7}, {%8,%9}, {%0,%1,%2,%3};"
        : "+f"(c[0]), "+f"(c[1]), "+f"(c[2]), "+f"(c[3])
        : "r"(a[0]), "r"(a[1]), "r"(a[2]), "r"(a[3]), "r"(b[0]), "r"(b[1]));
}

// ---------------- tf32 tensor-core GEMM core ----------------
// CTA tile 128x128, K-chunk 32, 256 threads (8 warps, 4x2), warp tile 32x64.
// A row-major [M,K] (optionally gathered rows), B row-major [K,N].
template<bool GATHER, bool BIAS, bool SILU, bool RESID>
__device__ __forceinline__ void gemm_tc(
    const float* __restrict__ A, int lda, const int* __restrict__ gidx,
    const float* __restrict__ B, int ldb,
    float* __restrict__ C, int ldc,
    const float* __restrict__ bias,
    const float* __restrict__ resid,
    int M, int K, int bm, int bn)
{
    __shared__ float As[128][36];   // [m][k] pad 36
    __shared__ float Bs[32][136];   // [k][n] pad 136

    const int tid  = threadIdx.x;
    const int wid  = tid >> 5;
    const int lane = tid & 31;
    const int warp_m = (wid >> 1) * 32;
    const int warp_n = (wid & 1) * 64;
    const int lr = lane >> 2;   // 0..7
    const int lc = lane & 3;    // 0..3

    float c[2][8][4];
#pragma unroll
    for (int mt = 0; mt < 2; mt++)
#pragma unroll
        for (int nt = 0; nt < 8; nt++)
#pragma unroll
            for (int i = 0; i < 4; i++) c[mt][nt][i] = 0.f;

    // A staging: thread covers rows am+32*i, k-quad ak4
    const int am  = tid >> 3;         // 0..31
    const int ak4 = (tid & 7) * 4;    // 0..28
    const float* aptr[4];
    bool aok[4];
#pragma unroll
    for (int i = 0; i < 4; i++) {
        int grow = bm + am + 32 * i;
        aok[i] = (grow < M);
        const float* p = A;
        if (aok[i]) p = A + (size_t)(GATHER ? gidx[grow] : grow) * lda;
        aptr[i] = p;
    }
    // B staging: thread covers k rows bk+8*i, n-quad bn4
    const int bk  = tid >> 5;         // 0..7
    const int bn4 = (tid & 31) * 4;   // 0..124

    float4 areg[4], breg[4];
    const float4 z4 = make_float4(0.f, 0.f, 0.f, 0.f);

    // prologue: load chunk 0
#pragma unroll
    for (int i = 0; i < 4; i++)
        areg[i] = aok[i] ? *(const float4*)(aptr[i] + ak4) : z4;
#pragma unroll
    for (int i = 0; i < 4; i++)
        breg[i] = *(const float4*)(B + (size_t)(bk + 8 * i) * ldb + bn + bn4);

    for (int k0 = 0; k0 < K; k0 += 32) {
        __syncthreads();   // previous compute done reading smem
        // store staged regs (converted to tf32) into smem
#pragma unroll
        for (int i = 0; i < 4; i++) {
            float4 v = areg[i];
            float4 w;
            w.x = __uint_as_float(f2tf32(v.x));
            w.y = __uint_as_float(f2tf32(v.y));
            w.z = __uint_as_float(f2tf32(v.z));
            w.w = __uint_as_float(f2tf32(v.w));
            *(float4*)&As[am + 32 * i][ak4] = w;
        }
#pragma unroll
        for (int i = 0; i < 4; i++) {
            float4 v = breg[i];
            float4 w;
            w.x = __uint_as_float(f2tf32(v.x));
            w.y = __uint_as_float(f2tf32(v.y));
            w.z = __uint_as_float(f2tf32(v.z));
            w.w = __uint_as_float(f2tf32(v.w));
            *(float4*)&Bs[bk + 8 * i][bn4] = w;
        }
        __syncthreads();

        // prefetch next chunk into regs
        if (k0 + 32 < K) {
            int kn = k0 + 32;
#pragma unroll
            for (int i = 0; i < 4; i++)
                areg[i] = aok[i] ? *(const float4*)(aptr[i] + kn + ak4) : z4;
#pragma unroll
            for (int i = 0; i < 4; i++)
                breg[i] = *(const float4*)(B + (size_t)(kn + bk + 8 * i) * ldb + bn + bn4);
        }

        // compute: 4 k8 steps
#pragma unroll
        for (int ks = 0; ks < 4; ks++) {
            const int kb = ks * 8;
            uint32_t a[2][4], b[8][2];
#pragma unroll
            for (int mt = 0; mt < 2; mt++) {
                int r = warp_m + mt * 16 + lr;
                a[mt][0] = __float_as_uint(As[r][kb + lc]);
                a[mt][1] = __float_as_uint(As[r + 8][kb + lc]);
                a[mt][2] = __float_as_uint(As[r][kb + 4 + lc]);
                a[mt][3] = __float_as_uint(As[r + 8][kb + 4 + lc]);
            }
#pragma unroll
            for (int nt = 0; nt < 8; nt++) {
                int col = warp_n + nt * 8 + lr;
                b[nt][0] = __float_as_uint(Bs[kb + lc][col]);
                b[nt][1] = __float_as_uint(Bs[kb + 4 + lc][col]);
            }
#pragma unroll
            for (int mt = 0; mt < 2; mt++)
#pragma unroll
                for (int nt = 0; nt < 8; nt++)
                    mma_tf32(c[mt][nt], a[mt], b[nt]);
        }
    }

    // epilogue
#pragma unroll
    for (int mt = 0; mt < 2; mt++) {
#pragma unroll
        for (int hh = 0; hh < 2; hh++) {
            int row = bm + warp_m + mt * 16 + hh * 8 + lr;
            if (row >= M) continue;
#pragma unroll
            for (int nt = 0; nt < 8; nt++) {
                int col = bn + warp_n + nt * 8 + 2 * lc;
                float v0 = c[mt][nt][2 * hh + 0];
                float v1 = c[mt][nt][2 * hh + 1];
                if (BIAS) { v0 += bias[col]; v1 += bias[col + 1]; }
                if (SILU) {
                    v0 = v0 / (1.f + expf(-v0));
                    v1 = v1 / (1.f + expf(-v1));
                }
                if (RESID) {
                    v0 += resid[(size_t)row * ldc + col];
                    v1 += resid[(size_t)row * ldc + col + 1];
                }
                float2 o = make_float2(v0, v1);
                *(float2*)&C[(size_t)row * ldc + col] = o;
            }
        }
    }
}

__global__ __launch_bounds__(256)
void k_gemm(const float* __restrict__ A, const float* __restrict__ B,
            float* __restrict__ C, int M, int N, int K)
{
    gemm_tc<false, false, false, false>(A, K, nullptr, B, N, C, N,
                                        nullptr, nullptr, M, K,
                                        blockIdx.y * 128, blockIdx.x * 128);
}

__global__ __launch_bounds__(256)
void k_gemm_resid(const float* __restrict__ A, const float* __restrict__ B,
                  float* __restrict__ C, const float* __restrict__ resid,
                  int M, int N, int K)
{
    gemm_tc<false, false, false, true>(A, K, nullptr, B, N, C, N,
                                       nullptr, resid, M, K,
                                       blockIdx.y * 128, blockIdx.x * 128);
}

__global__ __launch_bounds__(256)
void k_moe_up(const float* __restrict__ h, const float* __restrict__ w_up,
              const float* __restrict__ b_up)
{
    int e = blockIdx.z;
    int cnt = g_cnt[e];
    int off = g_off[e];
    int bm = blockIdx.y * 128;
    if (bm >= cnt) return;
    gemm_tc<true, true, true, false>(
        h, HD, g_tok + off,
        w_up + (size_t)e * HD * NI, NI,
        g_up + (size_t)off * NI, NI,
        b_up + (size_t)e * NI, nullptr,
        cnt, HD, bm, blockIdx.x * 128);
}

__global__ __launch_bounds__(256)
void k_moe_down(const float* __restrict__ w_down, const float* __restrict__ b_down)
{
    int e = blockIdx.z;
    int cnt = g_cnt[e];
    int off = g_off[e];
    int bm = blockIdx.y * 128;
    if (bm >= cnt) return;
    gemm_tc<false, true, false, false>(
        g_up + (size_t)off * NI, NI, nullptr,
        w_down + (size_t)e * NI * HD, HD,
        g_down + (size_t)off * HD, HD,
        b_down + (size_t)e * HD, nullptr,
        cnt, NI, bm, blockIdx.x * 128);
}

// ---------------- RMSNorm + RoPE on q and k (in place) ----------------
__global__ void k_norm_rope(float* __restrict__ q, float* __restrict__ k,
                            const float* __restrict__ qs, const float* __restrict__ ks)
{
    int t = blockIdx.x;
    int head = blockIdx.y;
    float* base;
    const float* scale;
    if (head < NHQ) { base = q + ((size_t)t * NHQ + head) * DH; scale = qs; }
    else            { base = k + ((size_t)t * NHKV + (head - NHQ)) * DH; scale = ks; }

    int d = threadIdx.x;
    float x = base[d];
    float ss = x * x;
#pragma unroll
    for (int o = 16; o; o >>= 1) ss += __shfl_xor_sync(0xffffffffu, ss, o);
    __shared__ float wsum[4];
    if ((d & 31) == 0) wsum[d >> 5] = ss;
    __syncthreads();
    float var = (wsum[0] + wsum[1] + wsum[2] + wsum[3]) * (1.f / 128.f);
    float inv = rsqrtf(var + 1e-6f);
    float xn = x * inv * scale[d];

    __shared__ float sh[128];
    sh[d] = xn;
    __syncthreads();

    int i = d & 63;
    float inv_freq = 1.f / powf(10000.f, (float)i / 64.f);
    float ang = (float)t * inv_freq;
    float c = cosf(ang), s = sinf(ang);
    float rot = (d < 64) ? -sh[d + 64] : sh[d - 64];
    base[d] = xn * c + rot * s;
}

// ---------------- causal flash attention (GQA 4:1), fp32 ----------------
__global__ __launch_bounds__(256)
void k_attn(const float* __restrict__ q, const float* __restrict__ k,
            const float* __restrict__ v, float* __restrict__ o)
{
    extern __shared__ float sm[];
    float* Qs = sm;                  // transposed [128][64]
    float* Ks = Qs + 128 * 64;       // transposed [128][64]
    float* Vs = Ks + 128 * 64;       // row-major [64][128]
    float* Ps = Vs + 64 * 128;       // padded [64][65]

    const int h  = blockIdx.y;
    const int kh = h >> 2;
    const int q0 = blockIdx.x * 64;
    const int tid = threadIdx.x;
    const int ty = tid >> 3;
    const int tx = tid & 7;
    const int r0 = ty * 2;
    const float scale = 0.08838834764831845f;

    for (int idx = tid; idx < 2048; idx += 256) {
        int r = idx & 63;
        int d4 = (idx >> 6) << 2;
        float4 val = *(const float4*)(q + (size_t)(q0 + r) * (NHQ * DH) + h * DH + d4);
        Qs[(d4 + 0) * 64 + r] = val.x;
        Qs[(d4 + 1) * 64 + r] = val.y;
        Qs[(d4 + 2) * 64 + r] = val.z;
        Qs[(d4 + 3) * 64 + r] = val.w;
    }

    float m0 = -FLT_MAX, m1 = -FLT_MAX, l0 = 0.f, l1 = 0.f;
    float oa0[16], oa1[16];
#pragma unroll
    for (int j = 0; j < 16; j++) { oa0[j] = 0.f; oa1[j] = 0.f; }

    const int ntiles = blockIdx.x + 1;
    for (int tile = 0; tile < ntiles; ++tile) {
        int k0 = tile * 64;
        for (int idx = tid; idx < 2048; idx += 256) {
            int r = idx & 63;
            int d4 = (idx >> 6) << 2;
            float4 val = *(const float4*)(k + (size_t)(k0 + r) * (NHKV * DH) + kh * DH + d4);
            Ks[(d4 + 0) * 64 + r] = val.x;
            Ks[(d4 + 1) * 64 + r] = val.y;
            Ks[(d4 + 2) * 64 + r] = val.z;
            Ks[(d4 + 3) * 64 + r] = val.w;
        }
        for (int idx = tid; idx < 2048; idx += 256) {
            int d4 = (idx & 31) * 4;
            int r = idx >> 5;
            float4 val = *(const float4*)(v + (size_t)(k0 + r) * (NHKV * DH) + kh * DH + d4);
            *(float4*)&Vs[r * 128 + d4] = val;
        }
        __syncthreads();

        float s0[8], s1[8];
#pragma unroll
        for (int j = 0; j < 8; j++) { s0[j] = 0.f; s1[j] = 0.f; }
#pragma unroll 4
        for (int kk = 0; kk < 128; ++kk) {
            float2 qv = *(const float2*)&Qs[kk * 64 + r0];
            float kf[8];
            *(float4*)(kf)     = *(const float4*)&Ks[kk * 64 + tx * 8];
            *(float4*)(kf + 4) = *(const float4*)&Ks[kk * 64 + tx * 8 + 4];
#pragma unroll
            for (int j = 0; j < 8; j++) {
                s0[j] += qv.x * kf[j];
                s1[j] += qv.y * kf[j];
            }
        }

        const bool diag = (tile == ntiles - 1);
        int qi0 = q0 + r0, qi1 = q0 + r0 + 1;
#pragma unroll
        for (int j = 0; j < 8; j++) {
            int kj = k0 + tx * 8 + j;
            s0[j] = (diag && kj > qi0) ? -FLT_MAX : s0[j] * scale;
            s1[j] = (diag && kj > qi1) ? -FLT_MAX : s1[j] * scale;
        }

        float tm0 = s0[0], tm1 = s1[0];
#pragma unroll
        for (int j = 1; j < 8; j++) { tm0 = fmaxf(tm0, s0[j]); tm1 = fmaxf(tm1, s1[j]); }
#pragma unroll
        for (int off = 1; off < 8; off <<= 1) {
            tm0 = fmaxf(tm0, __shfl_xor_sync(0xffffffffu, tm0, off));
            tm1 = fmaxf(tm1, __shfl_xor_sync(0xffffffffu, tm1, off));
        }
        float mn0 = fmaxf(m0, tm0), mn1 = fmaxf(m1, tm1);
        float a0 = expf(m0 - mn0), a1 = expf(m1 - mn1);

        float ps0 = 0.f, ps1 = 0.f;
#pragma unroll
        for (int j = 0; j < 8; j++) {
            s0[j] = expf(s0[j] - mn0);
            s1[j] = expf(s1[j] - mn1);
            ps0 += s0[j];
            ps1 += s1[j];
        }
#pragma unroll
        for (int off = 1; off < 8; off <<= 1) {
            ps0 += __shfl_xor_sync(0xffffffffu, ps0, off);
            ps1 += __shfl_xor_sync(0xffffffffu, ps1, off);
        }
        l0 = l0 * a0 + ps0;
        l1 = l1 * a1 + ps1;
        m0 = mn0; m1 = mn1;

#pragma unroll
        for (int j = 0; j < 16; j++) { oa0[j] *= a0; oa1[j] *= a1; }

#pragma unroll
        for (int j = 0; j < 8; j++) {
            Ps[r0 * 65 + tx * 8 + j]       = s0[j];
            Ps[(r0 + 1) * 65 + tx * 8 + j] = s1[j];
        }
        __syncthreads();

#pragma unroll 4
        for (int c = 0; c < 64; ++c) {
            float p0 = Ps[r0 * 65 + c];
            float p1 = Ps[r0 * 65 + 65 + c];
            float vf[16];
            *(float4*)(vf)      = *(const float4*)&Vs[c * 128 + tx * 16];
            *(float4*)(vf + 4)  = *(const float4*)&Vs[c * 128 + tx * 16 + 4];
            *(float4*)(vf + 8)  = *(const float4*)&Vs[c * 128 + tx * 16 + 8];
            *(float4*)(vf + 12) = *(const float4*)&Vs[c * 128 + tx * 16 + 12];
#pragma unroll
            for (int j = 0; j < 16; j++) {
                oa0[j] += p0 * vf[j];
                oa1[j] += p1 * vf[j];
            }
        }
        __syncthreads();
    }

    float inv0 = 1.f / l0, inv1 = 1.f / l1;
    size_t out0 = (size_t)(q0 + r0) * (NHQ * DH) + h * DH + tx * 16;
    size_t out1 = out0 + (NHQ * DH);
#pragma unroll
    for (int j = 0; j < 16; j++) {
        o[out0 + j] = oa0[j] * inv0;
        o[out1 + j] = oa1[j] * inv1;
    }
}

// ---------------- router + MoE routing ----------------
__global__ void k_router(const float* __restrict__ h, const float* __restrict__ w,
                         float* __restrict__ logits, float* __restrict__ out2)
{
    int t = blockIdx.x * 8 + (threadIdx.x >> 5);
    int lane = threadIdx.x & 31;
    const float* xr = h + (size_t)t * HD;
    float acc[NE];
#pragma unroll
    for (int e = 0; e < NE; e++) acc[e] = 0.f;
    for (int hh = lane; hh < HD; hh += 32) {
        float xv = xr[hh];
        const float* wr = w + hh * NE;
#pragma unroll
        for (int e = 0; e < NE; e++) acc[e] += xv * wr[e];
    }
#pragma unroll
    for (int e = 0; e < NE; e++)
#pragma unroll
        for (int o = 16; o; o >>= 1) acc[e] += __shfl_xor_sync(0xffffffffu, acc[e], o);
    if (lane == 0) {
#pragma unroll
        for (int e = 0; e < NE; e++) {
            logits[t * NE + e] = acc[e];
            out2[t * NE + e] = acc[e];
        }
    }
}

__global__ void k_zero_cnt()
{
    if (threadIdx.x < NE) g_cnt[threadIdx.x] = 0;
}

__global__ void k_top2(const float* __restrict__ logits)
{
    int t = blockIdx.x * 256 + threadIdx.x;
    if (t >= TT) return;
    const float* l = logits + t * NE;
    int i0 = 0; float v0 = l[0];
#pragma unroll
    for (int e = 1; e < NE; e++) { float v = l[e]; if (v > v0) { v0 = v; i0 = e; } }
    int i1 = -1; float v1 = -FLT_MAX;
#pragma unroll
    for (int e = 0; e < NE; e++) {
        if (e == i0) continue;
        float v = l[e];
        if (v > v1) { v1 = v; i1 = e; }
    }
    g_sel[t * 2] = i0;
    g_sel[t * 2 + 1] = i1;
    atomicAdd(&g_cnt[i0], 1);
    atomicAdd(&g_cnt[i1], 1);
}

__global__ void k_offsets()
{
    int s = 0;
    for (int e = 0; e < NE; e++) { g_off[e] = s; s += g_cnt[e]; g_fill[e] = 0; }
}

__global__ void k_fill()
{
    int t = blockIdx.x * 256 + threadIdx.x;
    if (t >= TT) return;
#pragma unroll
    for (int j = 0; j < 2; j++) {
        int e = g_sel[t * 2 + j];
        int pos = atomicAdd(&g_fill[e], 1);
        int slot = g_off[e] + pos;
        g_tok[slot] = t;
        g_slot[t * 2 + j] = slot;
    }
}

__global__ void k_final(float* __restrict__ out)
{
    size_t i = (size_t)blockIdx.x * 256 + threadIdx.x;
    int t = (int)(i >> 11);
    int c = (int)(i & 2047);
    int s0 = g_slot[t * 2];
    int s1 = g_slot[t * 2 + 1];
    out[i] = g_h[i] + g_down[(size_t)s0 * HD + c] + g_down[(size_t)s1 * HD + c];
}

// ---------------- launch ----------------
extern "C" void kernel_launch(void* const* d_in, const int* in_sizes, int n_in,
                              void* d_out, int out_size)
{
    const float* hidden   = (const float*)d_in[0];
    const float* wq       = (const float*)d_in[1];
    const float* wk       = (const float*)d_in[2];
    const float* wv       = (const float*)d_in[3];
    const float* wo       = (const float*)d_in[4];
    const float* q_scale  = (const float*)d_in[5];
    const float* k_scale  = (const float*)d_in[6];
    const float* router_w = (const float*)d_in[7];
    const float* w_up     = (const float*)d_in[8];
    const float* b_up     = (const float*)d_in[9];
    const float* w_down   = (const float*)d_in[10];
    const float* b_down   = (const float*)d_in[11];
    float* out = (float*)d_out;

    float *qb, *kb, *vb, *ab, *hb, *lb;
    cudaGetSymbolAddress((void**)&qb, g_q);
    cudaGetSymbolAddress((void**)&kb, g_k);
    cudaGetSymbolAddress((void**)&vb, g_v);
    cudaGetSymbolAddress((void**)&ab, g_attn);
    cudaGetSymbolAddress((void**)&hb, g_h);
    cudaGetSymbolAddress((void**)&lb, g_logits);

    // QKV projections (tf32 tensor cores)
    k_gemm<<<dim3(16, 16), 256>>>(hidden, wq, qb, TT, NHQ * DH, HD);
    k_gemm<<<dim3(4, 16), 256>>>(hidden, wk, kb, TT, NHKV * DH, HD);
    k_gemm<<<dim3(4, 16), 256>>>(hidden, wv, vb, TT, NHKV * DH, HD);

    // RMSNorm + RoPE
    k_norm_rope<<<dim3(TT, NHQ + NHKV), 128>>>(qb, kb, q_scale, k_scale);

    // flash attention (fp32)
    const int attn_smem = (128 * 64 + 128 * 64 + 64 * 128 + 64 * 65) * 4;
    cudaFuncSetAttribute(k_attn, cudaFuncAttributeMaxDynamicSharedMemorySize, attn_smem);
    k_attn<<<dim3(32, NHQ), 256, attn_smem>>>(qb, kb, vb, ab);

    // output projection + residual -> h
    k_gemm_resid<<<dim3(16, 16), 256>>>(ab, wo, hb, hidden, TT, HD, HD);

    // router
    k_router<<<TT / 8, 256>>>(hb, router_w, lb, out + (size_t)TT * HD);

    // routing
    k_zero_cnt<<<1, 32>>>();
    k_top2<<<TT / 256, 256>>>(lb);
    k_offsets<<<1, 1>>>();
    k_fill<<<TT / 256, 256>>>();

    // MoE grouped GEMMs (tf32 tensor cores)
    k_moe_up<<<dim3(NI / 128, 16, NE), 256>>>(hb, w_up, b_up);
    k_moe_down<<<dim3(HD / 128, 16, NE), 256>>>(w_down, b_down);

    // final combine
    k_final<<<(TT * HD) / 256, 256>>>(out);
}

// round 3
// speedup vs baseline: 4.0904x; 2.5210x over previous
#include <cuda_runtime.h>
#include <math.h>
#include <float.h>
#include <stdint.h>

// ---------------- problem constants ----------------
#define TT   2048
#define HD   2048
#define NHQ  16
#define NHKV 4
#define DH   128
#define NE   16
#define NI   768

// ---------------- device scratch ----------------
__device__ float g_q[TT * NHQ * DH];
__device__ float g_k[TT * NHKV * DH];
__device__ float g_v[TT * NHKV * DH];
__device__ float g_attn[TT * NHQ * DH];
__device__ float g_h[TT * HD];
__device__ float g_logits[TT * NE];
__device__ int   g_sel[TT * 2];
__device__ int   g_cnt[NE];
__device__ int   g_off[NE];
__device__ int   g_fill[NE];
__device__ int   g_tok[TT * 2];
__device__ int   g_slot[TT * 2];
__device__ float g_up[TT * 2 * NI];
__device__ float g_down[TT * 2 * HD];

// ---------------- tf32 helpers ----------------
__device__ __forceinline__ uint32_t f2tf32(float x) {
    uint32_t r;
    asm("cvt.rna.tf32.f32 %0, %1;" : "=r"(r) : "f"(x));
    return r;
}
__device__ __forceinline__ float tf(float x) { return __uint_as_float(f2tf32(x)); }

__device__ __forceinline__ void mma_tf32(float c[4], const uint32_t a[4], const uint32_t b[2]) {
    asm volatile(
        "mma.sync.aligned.m16n8k8.row.col.f32.tf32.tf32.f32 "
        "{%0,%1,%2,%3}, {%4,%5,%6,%7}, {%8,%9}, {%0,%1,%2,%3};"
        : "+f"(c[0]), "+f"(c[1]), "+f"(c[2]), "+f"(c[3])
        : "r"(a[0]), "r"(a[1]), "r"(a[2]), "r"(a[3]), "r"(b[0]), "r"(b[1]));
}

// ---------------- tf32 tensor-core GEMM core ----------------
template<bool GATHER, bool BIAS, bool SILU, bool RESID>
__device__ __forceinline__ void gemm_tc(
    const float* __restrict__ A, int lda, const int* __restrict__ gidx,
    const float* __restrict__ B, int ldb,
    float* __restrict__ C, int ldc,
    const float* __restrict__ bias,
    const float* __restrict__ resid,
    int M, int K, int bm, int bn)
{
    __shared__ float As[128][36];
    __shared__ float Bs[32][136];

    const int tid  = threadIdx.x;
    const int wid  = tid >> 5;
    const int lane = tid & 31;
    const int warp_m = (wid >> 1) * 32;
    const int warp_n = (wid & 1) * 64;
    const int lr = lane >> 2;
    const int lc = lane & 3;

    float c[2][8][4];
#pragma unroll
    for (int mt = 0; mt < 2; mt++)
#pragma unroll
        for (int nt = 0; nt < 8; nt++)
#pragma unroll
            for (int i = 0; i < 4; i++) c[mt][nt][i] = 0.f;

    const int am  = tid >> 3;
    const int ak4 = (tid & 7) * 4;
    const float* aptr[4];
    bool aok[4];
#pragma unroll
    for (int i = 0; i < 4; i++) {
        int grow = bm + am + 32 * i;
        aok[i] = (grow < M);
        const float* p = A;
        if (aok[i]) p = A + (size_t)(GATHER ? gidx[grow] : grow) * lda;
        aptr[i] = p;
    }
    const int bk  = tid >> 5;
    const int bn4 = (tid & 31) * 4;

    float4 areg[4], breg[4];
    const float4 z4 = make_float4(0.f, 0.f, 0.f, 0.f);

#pragma unroll
    for (int i = 0; i < 4; i++)
        areg[i] = aok[i] ? *(const float4*)(aptr[i] + ak4) : z4;
#pragma unroll
    for (int i = 0; i < 4; i++)
        breg[i] = *(const float4*)(B + (size_t)(bk + 8 * i) * ldb + bn + bn4);

    for (int k0 = 0; k0 < K; k0 += 32) {
        __syncthreads();
#pragma unroll
        for (int i = 0; i < 4; i++) {
            float4 v = areg[i];
            float4 w;
            w.x = tf(v.x); w.y = tf(v.y); w.z = tf(v.z); w.w = tf(v.w);
            *(float4*)&As[am + 32 * i][ak4] = w;
        }
#pragma unroll
        for (int i = 0; i < 4; i++) {
            float4 v = breg[i];
            float4 w;
            w.x = tf(v.x); w.y = tf(v.y); w.z = tf(v.z); w.w = tf(v.w);
            *(float4*)&Bs[bk + 8 * i][bn4] = w;
        }
        __syncthreads();

        if (k0 + 32 < K) {
            int kn = k0 + 32;
#pragma unroll
            for (int i = 0; i < 4; i++)
                areg[i] = aok[i] ? *(const float4*)(aptr[i] + kn + ak4) : z4;
#pragma unroll
            for (int i = 0; i < 4; i++)
                breg[i] = *(const float4*)(B + (size_t)(kn + bk + 8 * i) * ldb + bn + bn4);
        }

#pragma unroll
        for (int ks = 0; ks < 4; ks++) {
            const int kb = ks * 8;
            uint32_t a[2][4], b[8][2];
#pragma unroll
            for (int mt = 0; mt < 2; mt++) {
                int r = warp_m + mt * 16 + lr;
                a[mt][0] = __float_as_uint(As[r][kb + lc]);
                a[mt][1] = __float_as_uint(As[r + 8][kb + lc]);
                a[mt][2] = __float_as_uint(As[r][kb + 4 + lc]);
                a[mt][3] = __float_as_uint(As[r + 8][kb + 4 + lc]);
            }
#pragma unroll
            for (int nt = 0; nt < 8; nt++) {
                int col = warp_n + nt * 8 + lr;
                b[nt][0] = __float_as_uint(Bs[kb + lc][col]);
                b[nt][1] = __float_as_uint(Bs[kb + 4 + lc][col]);
            }
#pragma unroll
            for (int mt = 0; mt < 2; mt++)
#pragma unroll
                for (int nt = 0; nt < 8; nt++)
                    mma_tf32(c[mt][nt], a[mt], b[nt]);
        }
    }

#pragma unroll
    for (int mt = 0; mt < 2; mt++) {
#pragma unroll
        for (int hh = 0; hh < 2; hh++) {
            int row = bm + warp_m + mt * 16 + hh * 8 + lr;
            if (row >= M) continue;
#pragma unroll
            for (int nt = 0; nt < 8; nt++) {
                int col = bn + warp_n + nt * 8 + 2 * lc;
                float v0 = c[mt][nt][2 * hh + 0];
                float v1 = c[mt][nt][2 * hh + 1];
                if (BIAS) { v0 += bias[col]; v1 += bias[col + 1]; }
                if (SILU) {
                    v0 = v0 / (1.f + expf(-v0));
                    v1 = v1 / (1.f + expf(-v1));
                }
                if (RESID) {
                    v0 += resid[(size_t)row * ldc + col];
                    v1 += resid[(size_t)row * ldc + col + 1];
                }
                *(float2*)&C[(size_t)row * ldc + col] = make_float2(v0, v1);
            }
        }
    }
}

__global__ __launch_bounds__(256)
void k_gemm(const float* __restrict__ A, const float* __restrict__ B,
            float* __restrict__ C, int M, int N, int K)
{
    gemm_tc<false, false, false, false>(A, K, nullptr, B, N, C, N,
                                        nullptr, nullptr, M, K,
                                        blockIdx.y * 128, blockIdx.x * 128);
}

__global__ __launch_bounds__(256)
void k_gemm_resid(const float* __restrict__ A, const float* __restrict__ B,
                  float* __restrict__ C, const float* __restrict__ resid,
                  int M, int N, int K)
{
    gemm_tc<false, false, false, true>(A, K, nullptr, B, N, C, N,
                                       nullptr, resid, M, K,
                                       blockIdx.y * 128, blockIdx.x * 128);
}

__global__ __launch_bounds__(256)
void k_moe_up(const float* __restrict__ h, const float* __restrict__ w_up,
              const float* __restrict__ b_up)
{
    int e = blockIdx.z;
    int cnt = g_cnt[e];
    int off = g_off[e];
    int bm = blockIdx.y * 128;
    if (bm >= cnt) return;
    gemm_tc<true, true, true, false>(
        h, HD, g_tok + off,
        w_up + (size_t)e * HD * NI, NI,
        g_up + (size_t)off * NI, NI,
        b_up + (size_t)e * NI, nullptr,
        cnt, HD, bm, blockIdx.x * 128);
}

__global__ __launch_bounds__(256)
void k_moe_down(const float* __restrict__ w_down, const float* __restrict__ b_down)
{
    int e = blockIdx.z;
    int cnt = g_cnt[e];
    int off = g_off[e];
    int bm = blockIdx.y * 128;
    if (bm >= cnt) return;
    gemm_tc<false, true, false, false>(
        g_up + (size_t)off * NI, NI, nullptr,
        w_down + (size_t)e * NI * HD, HD,
        g_down + (size_t)off * HD, HD,
        b_down + (size_t)e * HD, nullptr,
        cnt, NI, bm, blockIdx.x * 128);
}

// ---------------- RMSNorm + RoPE ----------------
__global__ void k_norm_rope(float* __restrict__ q, float* __restrict__ k,
                            const float* __restrict__ qs, const float* __restrict__ ks)
{
    int t = blockIdx.x;
    int head = blockIdx.y;
    float* base;
    const float* scale;
    if (head < NHQ) { base = q + ((size_t)t * NHQ + head) * DH; scale = qs; }
    else            { base = k + ((size_t)t * NHKV + (head - NHQ)) * DH; scale = ks; }

    int d = threadIdx.x;
    float x = base[d];
    float ss = x * x;
#pragma unroll
    for (int o = 16; o; o >>= 1) ss += __shfl_xor_sync(0xffffffffu, ss, o);
    __shared__ float wsum[4];
    if ((d & 31) == 0) wsum[d >> 5] = ss;
    __syncthreads();
    float var = (wsum[0] + wsum[1] + wsum[2] + wsum[3]) * (1.f / 128.f);
    float inv = rsqrtf(var + 1e-6f);
    float xn = x * inv * scale[d];

    __shared__ float sh[128];
    sh[d] = xn;
    __syncthreads();

    int i = d & 63;
    float inv_freq = 1.f / powf(10000.f, (float)i / 64.f);
    float ang = (float)t * inv_freq;
    float c = cosf(ang), s = sinf(ang);
    float rot = (d < 64) ? -sh[d + 64] : sh[d - 64];
    base[d] = xn * c + rot * s;
}

// ---------------- tf32 tensor-core flash attention ----------------
// CTA: 128 q-rows x 64 k-cols tiles, 8 warps (16 q-rows each), D=128.
#define QLD 132
#define KLD 132
#define VLD 136
#define PLD 68

__global__ __launch_bounds__(256)
void k_attn_tc(const float* __restrict__ q, const float* __restrict__ k,
               const float* __restrict__ v, float* __restrict__ o)
{
    extern __shared__ float sm[];
    float* Qs = sm;                       // [128][132]
    float* Ks = Qs + 128 * QLD;           // [64][132]
    float* Vs = Ks + 64 * KLD;            // [64][136]
    float* Ps = Vs + 64 * VLD;            // [128][68]

    const int h  = blockIdx.y;
    const int kh = h >> 2;
    const int qt = gridDim.x - 1 - blockIdx.x;   // longest-first
    const int q0 = qt * 128;
    const int tid = threadIdx.x;
    const int wid = tid >> 5;
    const int lane = tid & 31;
    const int lr = lane >> 2;
    const int lc = lane & 3;
    const int wm = wid * 16;
    const float scale = 0.08838834764831845f;

    // load Q tile (tf32)
    for (int idx = tid; idx < 4096; idx += 256) {
        int r = idx >> 5;
        int d4 = (idx & 31) << 2;
        float4 val = *(const float4*)(q + (size_t)(q0 + r) * (NHQ * DH) + h * DH + d4);
        float4 w;
        w.x = tf(val.x); w.y = tf(val.y); w.z = tf(val.z); w.w = tf(val.w);
        *(float4*)&Qs[r * QLD + d4] = w;
    }

    float oacc[16][4];
#pragma unroll
    for (int nt = 0; nt < 16; nt++)
#pragma unroll
        for (int i = 0; i < 4; i++) oacc[nt][i] = 0.f;
    float m0 = -FLT_MAX, m1 = -FLT_MAX, l0 = 0.f, l1 = 0.f;

    const int r0g = q0 + wm + lr;
    const int r1g = r0g + 8;
    const int ntiles = 2 * qt + 2;

    for (int tile = 0; tile < ntiles; ++tile) {
        const int k0 = tile * 64;
        __syncthreads();
        // load K, V tiles (tf32)
        for (int idx = tid; idx < 2048; idx += 256) {
            int r = idx >> 5;
            int d4 = (idx & 31) << 2;
            float4 val = *(const float4*)(k + (size_t)(k0 + r) * (NHKV * DH) + kh * DH + d4);
            float4 w;
            w.x = tf(val.x); w.y = tf(val.y); w.z = tf(val.z); w.w = tf(val.w);
            *(float4*)&Ks[r * KLD + d4] = w;
        }
        for (int idx = tid; idx < 2048; idx += 256) {
            int r = idx >> 5;
            int d4 = (idx & 31) << 2;
            float4 val = *(const float4*)(v + (size_t)(k0 + r) * (NHKV * DH) + kh * DH + d4);
            float4 w;
            w.x = tf(val.x); w.y = tf(val.y); w.z = tf(val.z); w.w = tf(val.w);
            *(float4*)&Vs[r * VLD + d4] = w;
        }
        __syncthreads();

        // S = Q K^T : warp computes 16x64
        float sa[8][4];
#pragma unroll
        for (int nt = 0; nt < 8; nt++)
#pragma unroll
            for (int i = 0; i < 4; i++) sa[nt][i] = 0.f;

#pragma unroll
        for (int dk = 0; dk < 16; ++dk) {
            const int kb = dk * 8;
            uint32_t a[4];
            a[0] = __float_as_uint(Qs[(wm + lr) * QLD + kb + lc]);
            a[1] = __float_as_uint(Qs[(wm + lr + 8) * QLD + kb + lc]);
            a[2] = __float_as_uint(Qs[(wm + lr) * QLD + kb + 4 + lc]);
            a[3] = __float_as_uint(Qs[(wm + lr + 8) * QLD + kb + 4 + lc]);
#pragma unroll
            for (int nt = 0; nt < 8; nt++) {
                uint32_t b[2];
                b[0] = __float_as_uint(Ks[(nt * 8 + lr) * KLD + kb + lc]);
                b[1] = __float_as_uint(Ks[(nt * 8 + lr) * KLD + kb + 4 + lc]);
                mma_tf32(sa[nt], a, b);
            }
        }

        // mask + scale + row max
        float mx0 = -FLT_MAX, mx1 = -FLT_MAX;
#pragma unroll
        for (int nt = 0; nt < 8; nt++) {
            int cc = k0 + nt * 8 + 2 * lc;
            sa[nt][0] = (cc     <= r0g) ? sa[nt][0] * scale : -FLT_MAX;
            sa[nt][1] = (cc + 1 <= r0g) ? sa[nt][1] * scale : -FLT_MAX;
            sa[nt][2] = (cc     <= r1g) ? sa[nt][2] * scale : -FLT_MAX;
            sa[nt][3] = (cc + 1 <= r1g) ? sa[nt][3] * scale : -FLT_MAX;
            mx0 = fmaxf(mx0, fmaxf(sa[nt][0], sa[nt][1]));
            mx1 = fmaxf(mx1, fmaxf(sa[nt][2], sa[nt][3]));
        }
        mx0 = fmaxf(mx0, __shfl_xor_sync(0xffffffffu, mx0, 1));
        mx0 = fmaxf(mx0, __shfl_xor_sync(0xffffffffu, mx0, 2));
        mx1 = fmaxf(mx1, __shfl_xor_sync(0xffffffffu, mx1, 1));
        mx1 = fmaxf(mx1, __shfl_xor_sync(0xffffffffu, mx1, 2));

        float mn0 = fmaxf(m0, mx0), mn1 = fmaxf(m1, mx1);
        float al0 = expf(m0 - mn0), al1 = expf(m1 - mn1);

        float ps0 = 0.f, ps1 = 0.f;
#pragma unroll
        for (int nt = 0; nt < 8; nt++) {
            sa[nt][0] = expf(sa[nt][0] - mn0);
            sa[nt][1] = expf(sa[nt][1] - mn0);
            sa[nt][2] = expf(sa[nt][2] - mn1);
            sa[nt][3] = expf(sa[nt][3] - mn1);
            ps0 += sa[nt][0] + sa[nt][1];
            ps1 += sa[nt][2] + sa[nt][3];
        }
        ps0 += __shfl_xor_sync(0xffffffffu, ps0, 1);
        ps0 += __shfl_xor_sync(0xffffffffu, ps0, 2);
        ps1 += __shfl_xor_sync(0xffffffffu, ps1, 1);
        ps1 += __shfl_xor_sync(0xffffffffu, ps1, 2);

        l0 = l0 * al0 + ps0;
        l1 = l1 * al1 + ps1;
        m0 = mn0; m1 = mn1;

#pragma unroll
        for (int nt = 0; nt < 16; nt++) {
            oacc[nt][0] *= al0; oacc[nt][1] *= al0;
            oacc[nt][2] *= al1; oacc[nt][3] *= al1;
        }

        // write P (tf32) to warp-private smem rows
#pragma unroll
        for (int nt = 0; nt < 8; nt++) {
            int cc = nt * 8 + 2 * lc;
            *(float2*)&Ps[(wm + lr) * PLD + cc]     = make_float2(tf(sa[nt][0]), tf(sa[nt][1]));
            *(float2*)&Ps[(wm + lr + 8) * PLD + cc] = make_float2(tf(sa[nt][2]), tf(sa[nt][3]));
        }
        __syncwarp();

        // O += P V : warp computes 16x128
#pragma unroll
        for (int kc = 0; kc < 8; ++kc) {
            const int kb = kc * 8;
            uint32_t a[4];
            a[0] = __float_as_uint(Ps[(wm + lr) * PLD + kb + lc]);
            a[1] = __float_as_uint(Ps[(wm + lr + 8) * PLD + kb + lc]);
            a[2] = __float_as_uint(Ps[(wm + lr) * PLD + kb + 4 + lc]);
            a[3] = __float_as_uint(Ps[(wm + lr + 8) * PLD + kb + 4 + lc]);
#pragma unroll
            for (int nt = 0; nt < 16; nt++) {
                uint32_t b[2];
                b[0] = __float_as_uint(Vs[(kb + lc) * VLD + nt * 8 + lr]);
                b[1] = __float_as_uint(Vs[(kb + 4 + lc) * VLD + nt * 8 + lr]);
                mma_tf32(oacc[nt], a, b);
            }
        }
        __syncwarp();
    }

    float inv0 = 1.f / l0, inv1 = 1.f / l1;
#pragma unroll
    for (int nt = 0; nt < 16; nt++) {
        int cc = nt * 8 + 2 * lc;
        size_t o0 = (size_t)r0g * (NHQ * DH) + h * DH + cc;
        size_t o1 = (size_t)r1g * (NHQ * DH) + h * DH + cc;
        *(float2*)&o[o0] = make_float2(oacc[nt][0] * inv0, oacc[nt][1] * inv0);
        *(float2*)&o[o1] = make_float2(oacc[nt][2] * inv1, oacc[nt][3] * inv1);
    }
}

// ---------------- router + MoE routing ----------------
__global__ void k_router(const float* __restrict__ h, const float* __restrict__ w,
                         float* __restrict__ logits, float* __restrict__ out2)
{
    int t = blockIdx.x * 8 + (threadIdx.x >> 5);
    int lane = threadIdx.x & 31;
    const float* xr = h + (size_t)t * HD;
    float acc[NE];
#pragma unroll
    for (int e = 0; e < NE; e++) acc[e] = 0.f;
    for (int hh = lane; hh < HD; hh += 32) {
        float xv = xr[hh];
        const float* wr = w + hh * NE;
#pragma unroll
        for (int e = 0; e < NE; e++) acc[e] += xv * wr[e];
    }
#pragma unroll
    for (int e = 0; e < NE; e++)
#pragma unroll
        for (int o = 16; o; o >>= 1) acc[e] += __shfl_xor_sync(0xffffffffu, acc[e], o);
    if (lane == 0) {
#pragma unroll
        for (int e = 0; e < NE; e++) {
            logits[t * NE + e] = acc[e];
            out2[t * NE + e] = acc[e];
        }
    }
}

__global__ void k_zero_cnt()
{
    if (threadIdx.x < NE) g_cnt[threadIdx.x] = 0;
}

__global__ void k_top2(const float* __restrict__ logits)
{
    int t = blockIdx.x * 256 + threadIdx.x;
    if (t >= TT) return;
    const float* l = logits + t * NE;
    int i0 = 0; float v0 = l[0];
#pragma unroll
    for (int e = 1; e < NE; e++) { float v = l[e]; if (v > v0) { v0 = v; i0 = e; } }
    int i1 = -1; float v1 = -FLT_MAX;
#pragma unroll
    for (int e = 0; e < NE; e++) {
        if (e == i0) continue;
        float v = l[e];
        if (v > v1) { v1 = v; i1 = e; }
    }
    g_sel[t * 2] = i0;
    g_sel[t * 2 + 1] = i1;
    atomicAdd(&g_cnt[i0], 1);
    atomicAdd(&g_cnt[i1], 1);
}

__global__ void k_offsets()
{
    int s = 0;
    for (int e = 0; e < NE; e++) { g_off[e] = s; s += g_cnt[e]; g_fill[e] = 0; }
}

__global__ void k_fill()
{
    int t = blockIdx.x * 256 + threadIdx.x;
    if (t >= TT) return;
#pragma unroll
    for (int j = 0; j < 2; j++) {
        int e = g_sel[t * 2 + j];
        int pos = atomicAdd(&g_fill[e], 1);
        int slot = g_off[e] + pos;
        g_tok[slot] = t;
        g_slot[t * 2 + j] = slot;
    }
}

__global__ void k_final(float* __restrict__ out)
{
    size_t i = (size_t)blockIdx.x * 256 + threadIdx.x;
    int t = (int)(i >> 11);
    int c = (int)(i & 2047);
    int s0 = g_slot[t * 2];
    int s1 = g_slot[t * 2 + 1];
    out[i] = g_h[i] + g_down[(size_t)s0 * HD + c] + g_down[(size_t)s1 * HD + c];
}

// ---------------- launch ----------------
extern "C" void kernel_launch(void* const* d_in, const int* in_sizes, int n_in,
                              void* d_out, int out_size)
{
    const float* hidden   = (const float*)d_in[0];
    const float* wq       = (const float*)d_in[1];
    const float* wk       = (const float*)d_in[2];
    const float* wv       = (const float*)d_in[3];
    const float* wo       = (const float*)d_in[4];
    const float* q_scale  = (const float*)d_in[5];
    const float* k_scale  = (const float*)d_in[6];
    const float* router_w = (const float*)d_in[7];
    const float* w_up     = (const float*)d_in[8];
    const float* b_up     = (const float*)d_in[9];
    const float* w_down   = (const float*)d_in[10];
    const float* b_down   = (const float*)d_in[11];
    float* out = (float*)d_out;

    float *qb, *kb, *vb, *ab, *hb, *lb;
    cudaGetSymbolAddress((void**)&qb, g_q);
    cudaGetSymbolAddress((void**)&kb, g_k);
    cudaGetSymbolAddress((void**)&vb, g_v);
    cudaGetSymbolAddress((void**)&ab, g_attn);
    cudaGetSymbolAddress((void**)&hb, g_h);
    cudaGetSymbolAddress((void**)&lb, g_logits);

    k_gemm<<<dim3(16, 16), 256>>>(hidden, wq, qb, TT, NHQ * DH, HD);
    k_gemm<<<dim3(4, 16), 256>>>(hidden, wk, kb, TT, NHKV * DH, HD);
    k_gemm<<<dim3(4, 16), 256>>>(hidden, wv, vb, TT, NHKV * DH, HD);

    k_norm_rope<<<dim3(TT, NHQ + NHKV), 128>>>(qb, kb, q_scale, k_scale);

    // tf32 tensor-core flash attention
    const int attn_smem = (128 * QLD + 64 * KLD + 64 * VLD + 128 * PLD) * 4;
    cudaFuncSetAttribute(k_attn_tc, cudaFuncAttributeMaxDynamicSharedMemorySize, attn_smem);
    k_attn_tc<<<dim3(16, NHQ), 256, attn_smem>>>(qb, kb, vb, ab);

    k_gemm_resid<<<dim3(16, 16), 256>>>(ab, wo, hb, hidden, TT, HD, HD);

    k_router<<<TT / 8, 256>>>(hb, router_w, lb, out + (size_t)TT * HD);

    k_zero_cnt<<<1, 32>>>();
    k_top2<<<TT / 256, 256>>>(lb);
    k_offsets<<<1, 1>>>();
    k_fill<<<TT / 256, 256>>>();

    k_moe_up<<<dim3(NI / 128, 16, NE), 256>>>(hb, w_up, b_up);
    k_moe_down<<<dim3(HD / 128, 16, NE), 256>>>(w_down, b_down);

    k_final<<<(TT * HD) / 256, 256>>>(out);
}

// round 4
// speedup vs baseline: 5.3164x; 1.2997x over previous
#include <cuda_runtime.h>
#include <math.h>
#include <float.h>
#include <stdint.h>

// ---------------- problem constants ----------------
#define TT   2048
#define HD   2048
#define NHQ  16
#define NHKV 4
#define DH   128
#define NE   16
#define NI   768

// ---------------- device scratch ----------------
__device__ float g_q[TT * NHQ * DH];
__device__ float g_k[TT * NHKV * DH];
__device__ float g_v[TT * NHKV * DH];
__device__ float g_attn[TT * NHQ * DH];
__device__ float g_h[TT * HD];
__device__ float g_logits[TT * NE];
__device__ int   g_sel[TT * 2];
__device__ int   g_cnt[NE];
__device__ int   g_off[NE];
__device__ int   g_fill[NE];
__device__ int   g_tok[TT * 2];
__device__ int   g_slot[TT * 2];
__device__ float g_up[TT * 2 * NI];
__device__ float g_down[TT * 2 * HD];

// ---------------- tf32 / cp.async helpers ----------------
__device__ __forceinline__ uint32_t f2tf32(float x) {
    uint32_t r;
    asm("cvt.rna.tf32.f32 %0, %1;" : "=r"(r) : "f"(x));
    return r;
}
__device__ __forceinline__ float tf(float x) { return __uint_as_float(f2tf32(x)); }

__device__ __forceinline__ void mma_tf32(float c[4], const uint32_t a[4], const uint32_t b[2]) {
    asm volatile(
        "mma.sync.aligned.m16n8k8.row.col.f32.tf32.tf32.f32 "
        "{%0,%1,%2,%3}, {%4,%5,%6,%7}, {%8,%9}, {%0,%1,%2,%3};"
        : "+f"(c[0]), "+f"(c[1]), "+f"(c[2]), "+f"(c[3])
        : "r"(a[0]), "r"(a[1]), "r"(a[2]), "r"(a[3]), "r"(b[0]), "r"(b[1]));
}

__device__ __forceinline__ void cpa16(uint32_t dst, const void* src, bool pred) {
    int sz = pred ? 16 : 0;
    asm volatile("cp.async.cg.shared.global [%0], [%1], 16, %2;\n"
                 :: "r"(dst), "l"(src), "r"(sz));
}
__device__ __forceinline__ void cp_commit() {
    asm volatile("cp.async.commit_group;\n" ::: "memory");
}
__device__ __forceinline__ void cp_wait0() {
    asm volatile("cp.async.wait_group 0;\n" ::: "memory");
}

// ---------------- tf32 tensor-core GEMM core (cp.async double-buffered) ----------------
#define AST 36
#define BST 136
#define ASZ (128 * AST)
#define BSZ (32 * BST)
#define GEMM_SMEM ((2 * ASZ + 2 * BSZ) * 4)

template<bool GATHER, bool BIAS, bool SILU, bool RESID>
__device__ __forceinline__ void gemm_tc(
    const float* __restrict__ A, int lda, const int* __restrict__ gidx,
    const float* __restrict__ B, int ldb,
    float* __restrict__ C, int ldc,
    const float* __restrict__ bias,
    const float* __restrict__ resid,
    int M, int K, int bm, int bn)
{
    extern __shared__ float smem[];
    float* As = smem;               // [2][128][AST]
    float* Bs = smem + 2 * ASZ;     // [2][32][BST]

    const int tid  = threadIdx.x;
    const int wid  = tid >> 5;
    const int lane = tid & 31;
    const int warp_m = (wid >> 1) * 32;
    const int warp_n = (wid & 1) * 64;
    const int lr = lane >> 2;
    const int lc = lane & 3;

    float c[2][8][4];
#pragma unroll
    for (int mt = 0; mt < 2; mt++)
#pragma unroll
        for (int nt = 0; nt < 8; nt++)
#pragma unroll
            for (int i = 0; i < 4; i++) c[mt][nt][i] = 0.f;

    const int am  = tid >> 3;        // 0..31 (rows am+32i)
    const int ak4 = (tid & 7) * 4;   // k-quad
    const int bk  = tid >> 5;        // 0..7 (k rows bk+8i)
    const int bn4 = (tid & 31) * 4;  // n-quad

    const float* asrc[4];
    bool aok[4];
#pragma unroll
    for (int i = 0; i < 4; i++) {
        int grow = bm + am + 32 * i;
        aok[i] = (grow < M);
        const float* p = A;
        if (aok[i]) p = A + (size_t)(GATHER ? gidx[grow] : grow) * lda;
        asrc[i] = p + ak4;
    }
    const float* bsrc[4];
#pragma unroll
    for (int i = 0; i < 4; i++)
        bsrc[i] = B + (size_t)(bk + 8 * i) * ldb + bn + bn4;

    uint32_t sa = (uint32_t)__cvta_generic_to_shared(As);
    uint32_t sb = (uint32_t)__cvta_generic_to_shared(Bs);
    uint32_t adst[4], bdst[4];
#pragma unroll
    for (int i = 0; i < 4; i++) {
        adst[i] = sa + ((am + 32 * i) * AST + ak4) * 4;
        bdst[i] = sb + ((bk + 8 * i) * BST + bn4) * 4;
    }

    // stage 0
#pragma unroll
    for (int i = 0; i < 4; i++) cpa16(adst[i], asrc[i], aok[i]);
#pragma unroll
    for (int i = 0; i < 4; i++) cpa16(bdst[i], bsrc[i], true);
    cp_commit();

    const int nch = K >> 5;
    for (int ch = 0; ch < nch; ch++) {
        cp_wait0();
        __syncthreads();

        if (ch + 1 < nch) {
            const int koff = (ch + 1) * 32;
            const uint32_t ao = ((ch + 1) & 1) ? ASZ * 4 : 0;
            const uint32_t bo = ((ch + 1) & 1) ? BSZ * 4 : 0;
#pragma unroll
            for (int i = 0; i < 4; i++) cpa16(adst[i] + ao, asrc[i] + koff, aok[i]);
#pragma unroll
            for (int i = 0; i < 4; i++) cpa16(bdst[i] + bo, bsrc[i] + (size_t)koff * ldb, true);
            cp_commit();
        }

        const float* Ac = As + (ch & 1) * ASZ;
        const float* Bc = Bs + (ch & 1) * BSZ;

#pragma unroll
        for (int ks = 0; ks < 4; ks++) {
            const int kb = ks * 8;
            uint32_t a[2][4], b[8][2];
#pragma unroll
            for (int mt = 0; mt < 2; mt++) {
                int r = warp_m + mt * 16 + lr;
                a[mt][0] = __float_as_uint(Ac[r * AST + kb + lc]);
                a[mt][1] = __float_as_uint(Ac[(r + 8) * AST + kb + lc]);
                a[mt][2] = __float_as_uint(Ac[r * AST + kb + 4 + lc]);
                a[mt][3] = __float_as_uint(Ac[(r + 8) * AST + kb + 4 + lc]);
            }
#pragma unroll
            for (int nt = 0; nt < 8; nt++) {
                int col = warp_n + nt * 8 + lr;
                b[nt][0] = __float_as_uint(Bc[(kb + lc) * BST + col]);
                b[nt][1] = __float_as_uint(Bc[(kb + 4 + lc) * BST + col]);
            }
#pragma unroll
            for (int mt = 0; mt < 2; mt++)
#pragma unroll
                for (int nt = 0; nt < 8; nt++)
                    mma_tf32(c[mt][nt], a[mt], b[nt]);
        }
    }

#pragma unroll
    for (int mt = 0; mt < 2; mt++) {
#pragma unroll
        for (int hh = 0; hh < 2; hh++) {
            int row = bm + warp_m + mt * 16 + hh * 8 + lr;
            if (row >= M) continue;
#pragma unroll
            for (int nt = 0; nt < 8; nt++) {
                int col = bn + warp_n + nt * 8 + 2 * lc;
                float v0 = c[mt][nt][2 * hh + 0];
                float v1 = c[mt][nt][2 * hh + 1];
                if (BIAS) { v0 += bias[col]; v1 += bias[col + 1]; }
                if (SILU) {
                    v0 = v0 / (1.f + expf(-v0));
                    v1 = v1 / (1.f + expf(-v1));
                }
                if (RESID) {
                    v0 += resid[(size_t)row * ldc + col];
                    v1 += resid[(size_t)row * ldc + col + 1];
                }
                *(float2*)&C[(size_t)row * ldc + col] = make_float2(v0, v1);
            }
        }
    }
}

// fused Q/K/V projection: grid (24, 16)
__global__ __launch_bounds__(256, 2)
void k_qkv(const float* __restrict__ x,
           const float* __restrict__ wq, const float* __restrict__ wk,
           const float* __restrict__ wv,
           float* __restrict__ q, float* __restrict__ k, float* __restrict__ v)
{
    const int bx = blockIdx.x;
    const int bm = blockIdx.y * 128;
    if (bx < 16)
        gemm_tc<false, false, false, false>(x, HD, nullptr, wq, NHQ * DH, q, NHQ * DH,
                                            nullptr, nullptr, TT, HD, bm, bx * 128);
    else if (bx < 20)
        gemm_tc<false, false, false, false>(x, HD, nullptr, wk, NHKV * DH, k, NHKV * DH,
                                            nullptr, nullptr, TT, HD, bm, (bx - 16) * 128);
    else
        gemm_tc<false, false, false, false>(x, HD, nullptr, wv, NHKV * DH, v, NHKV * DH,
                                            nullptr, nullptr, TT, HD, bm, (bx - 20) * 128);
}

__global__ __launch_bounds__(256, 2)
void k_gemm_resid(const float* __restrict__ A, const float* __restrict__ B,
                  float* __restrict__ C, const float* __restrict__ resid,
                  int M, int N, int K)
{
    gemm_tc<false, false, false, true>(A, K, nullptr, B, N, C, N,
                                       nullptr, resid, M, K,
                                       blockIdx.y * 128, blockIdx.x * 128);
}

__global__ __launch_bounds__(256, 2)
void k_moe_up(const float* __restrict__ h, const float* __restrict__ w_up,
              const float* __restrict__ b_up)
{
    int e = blockIdx.z;
    int cnt = g_cnt[e];
    int off = g_off[e];
    int bm = blockIdx.y * 128;
    if (bm >= cnt) return;
    gemm_tc<true, true, true, false>(
        h, HD, g_tok + off,
        w_up + (size_t)e * HD * NI, NI,
        g_up + (size_t)off * NI, NI,
        b_up + (size_t)e * NI, nullptr,
        cnt, HD, bm, blockIdx.x * 128);
}

__global__ __launch_bounds__(256, 2)
void k_moe_down(const float* __restrict__ w_down, const float* __restrict__ b_down)
{
    int e = blockIdx.z;
    int cnt = g_cnt[e];
    int off = g_off[e];
    int bm = blockIdx.y * 128;
    if (bm >= cnt) return;
    gemm_tc<false, true, false, false>(
        g_up + (size_t)off * NI, NI, nullptr,
        w_down + (size_t)e * NI * HD, HD,
        g_down + (size_t)off * HD, HD,
        b_down + (size_t)e * HD, nullptr,
        cnt, NI, bm, blockIdx.x * 128);
}

// ---------------- RMSNorm + RoPE ----------------
__global__ void k_norm_rope(float* __restrict__ q, float* __restrict__ k,
                            const float* __restrict__ qs, const float* __restrict__ ks)
{
    int t = blockIdx.x;
    int head = blockIdx.y;
    float* base;
    const float* scale;
    if (head < NHQ) { base = q + ((size_t)t * NHQ + head) * DH; scale = qs; }
    else            { base = k + ((size_t)t * NHKV + (head - NHQ)) * DH; scale = ks; }

    int d = threadIdx.x;
    float x = base[d];
    float ss = x * x;
#pragma unroll
    for (int o = 16; o; o >>= 1) ss += __shfl_xor_sync(0xffffffffu, ss, o);
    __shared__ float wsum[4];
    if ((d & 31) == 0) wsum[d >> 5] = ss;
    __syncthreads();
    float var = (wsum[0] + wsum[1] + wsum[2] + wsum[3]) * (1.f / 128.f);
    float inv = rsqrtf(var + 1e-6f);
    float xn = x * inv * scale[d];

    __shared__ float sh[128];
    sh[d] = xn;
    __syncthreads();

    int i = d & 63;
    float inv_freq = 1.f / powf(10000.f, (float)i / 64.f);
    float ang = (float)t * inv_freq;
    float c = cosf(ang), s = sinf(ang);
    float rot = (d < 64) ? -sh[d + 64] : sh[d - 64];
    base[d] = xn * c + rot * s;
}

// ---------------- tf32 tensor-core flash attention ----------------
#define QLD 132
#define KLD 132
#define VLD 136
#define PLD 68

__global__ __launch_bounds__(256)
void k_attn_tc(const float* __restrict__ q, const float* __restrict__ k,
               const float* __restrict__ v, float* __restrict__ o)
{
    extern __shared__ float sm[];
    float* Qs = sm;                       // [128][132]
    float* Ks = Qs + 128 * QLD;           // [64][132]
    float* Vs = Ks + 64 * KLD;            // [64][136]
    float* Ps = Vs + 64 * VLD;            // [128][68]

    const int h  = blockIdx.y;
    const int kh = h >> 2;
    const int qt = gridDim.x - 1 - blockIdx.x;
    const int q0 = qt * 128;
    const int tid = threadIdx.x;
    const int wid = tid >> 5;
    const int lane = tid & 31;
    const int lr = lane >> 2;
    const int lc = lane & 3;
    const int wm = wid * 16;
    const float scale = 0.08838834764831845f;

    for (int idx = tid; idx < 4096; idx += 256) {
        int r = idx >> 5;
        int d4 = (idx & 31) << 2;
        float4 val = *(const float4*)(q + (size_t)(q0 + r) * (NHQ * DH) + h * DH + d4);
        float4 w;
        w.x = tf(val.x); w.y = tf(val.y); w.z = tf(val.z); w.w = tf(val.w);
        *(float4*)&Qs[r * QLD + d4] = w;
    }

    float oacc[16][4];
#pragma unroll
    for (int nt = 0; nt < 16; nt++)
#pragma unroll
        for (int i = 0; i < 4; i++) oacc[nt][i] = 0.f;
    float m0 = -FLT_MAX, m1 = -FLT_MAX, l0 = 0.f, l1 = 0.f;

    const int r0g = q0 + wm + lr;
    const int r1g = r0g + 8;
    const int ntiles = 2 * qt + 2;

    for (int tile = 0; tile < ntiles; ++tile) {
        const int k0 = tile * 64;
        __syncthreads();
        for (int idx = tid; idx < 2048; idx += 256) {
            int r = idx >> 5;
            int d4 = (idx & 31) << 2;
            float4 val = *(const float4*)(k + (size_t)(k0 + r) * (NHKV * DH) + kh * DH + d4);
            float4 w;
            w.x = tf(val.x); w.y = tf(val.y); w.z = tf(val.z); w.w = tf(val.w);
            *(float4*)&Ks[r * KLD + d4] = w;
        }
        for (int idx = tid; idx < 2048; idx += 256) {
            int r = idx >> 5;
            int d4 = (idx & 31) << 2;
            float4 val = *(const float4*)(v + (size_t)(k0 + r) * (NHKV * DH) + kh * DH + d4);
            float4 w;
            w.x = tf(val.x); w.y = tf(val.y); w.z = tf(val.z); w.w = tf(val.w);
            *(float4*)&Vs[r * VLD + d4] = w;
        }
        __syncthreads();

        float sa[8][4];
#pragma unroll
        for (int nt = 0; nt < 8; nt++)
#pragma unroll
            for (int i = 0; i < 4; i++) sa[nt][i] = 0.f;

#pragma unroll
        for (int dk = 0; dk < 16; ++dk) {
            const int kb = dk * 8;
            uint32_t a[4];
            a[0] = __float_as_uint(Qs[(wm + lr) * QLD + kb + lc]);
            a[1] = __float_as_uint(Qs[(wm + lr + 8) * QLD + kb + lc]);
            a[2] = __float_as_uint(Qs[(wm + lr) * QLD + kb + 4 + lc]);
            a[3] = __float_as_uint(Qs[(wm + lr + 8) * QLD + kb + 4 + lc]);
#pragma unroll
            for (int nt = 0; nt < 8; nt++) {
                uint32_t b[2];
                b[0] = __float_as_uint(Ks[(nt * 8 + lr) * KLD + kb + lc]);
                b[1] = __float_as_uint(Ks[(nt * 8 + lr) * KLD + kb + 4 + lc]);
                mma_tf32(sa[nt], a, b);
            }
        }

        float mx0 = -FLT_MAX, mx1 = -FLT_MAX;
#pragma unroll
        for (int nt = 0; nt < 8; nt++) {
            int cc = k0 + nt * 8 + 2 * lc;
            sa[nt][0] = (cc     <= r0g) ? sa[nt][0] * scale : -FLT_MAX;
            sa[nt][1] = (cc + 1 <= r0g) ? sa[nt][1] * scale : -FLT_MAX;
            sa[nt][2] = (cc     <= r1g) ? sa[nt][2] * scale : -FLT_MAX;
            sa[nt][3] = (cc + 1 <= r1g) ? sa[nt][3] * scale : -FLT_MAX;
            mx0 = fmaxf(mx0, fmaxf(sa[nt][0], sa[nt][1]));
            mx1 = fmaxf(mx1, fmaxf(sa[nt][2], sa[nt][3]));
        }
        mx0 = fmaxf(mx0, __shfl_xor_sync(0xffffffffu, mx0, 1));
        mx0 = fmaxf(mx0, __shfl_xor_sync(0xffffffffu, mx0, 2));
        mx1 = fmaxf(mx1, __shfl_xor_sync(0xffffffffu, mx1, 1));
        mx1 = fmaxf(mx1, __shfl_xor_sync(0xffffffffu, mx1, 2));

        float mn0 = fmaxf(m0, mx0), mn1 = fmaxf(m1, mx1);
        float al0 = expf(m0 - mn0), al1 = expf(m1 - mn1);

        float ps0 = 0.f, ps1 = 0.f;
#pragma unroll
        for (int nt = 0; nt < 8; nt++) {
            sa[nt][0] = expf(sa[nt][0] - mn0);
            sa[nt][1] = expf(sa[nt][1] - mn0);
            sa[nt][2] = expf(sa[nt][2] - mn1);
            sa[nt][3] = expf(sa[nt][3] - mn1);
            ps0 += sa[nt][0] + sa[nt][1];
            ps1 += sa[nt][2] + sa[nt][3];
        }
        ps0 += __shfl_xor_sync(0xffffffffu, ps0, 1);
        ps0 += __shfl_xor_sync(0xffffffffu, ps0, 2);
        ps1 += __shfl_xor_sync(0xffffffffu, ps1, 1);
        ps1 += __shfl_xor_sync(0xffffffffu, ps1, 2);

        l0 = l0 * al0 + ps0;
        l1 = l1 * al1 + ps1;
        m0 = mn0; m1 = mn1;

#pragma unroll
        for (int nt = 0; nt < 16; nt++) {
            oacc[nt][0] *= al0; oacc[nt][1] *= al0;
            oacc[nt][2] *= al1; oacc[nt][3] *= al1;
        }

#pragma unroll
        for (int nt = 0; nt < 8; nt++) {
            int cc = nt * 8 + 2 * lc;
            *(float2*)&Ps[(wm + lr) * PLD + cc]     = make_float2(tf(sa[nt][0]), tf(sa[nt][1]));
            *(float2*)&Ps[(wm + lr + 8) * PLD + cc] = make_float2(tf(sa[nt][2]), tf(sa[nt][3]));
        }
        __syncwarp();

#pragma unroll
        for (int kc = 0; kc < 8; ++kc) {
            const int kb = kc * 8;
            uint32_t a[4];
            a[0] = __float_as_uint(Ps[(wm + lr) * PLD + kb + lc]);
            a[1] = __float_as_uint(Ps[(wm + lr + 8) * PLD + kb + lc]);
            a[2] = __float_as_uint(Ps[(wm + lr) * PLD + kb + 4 + lc]);
            a[3] = __float_as_uint(Ps[(wm + lr + 8) * PLD + kb + 4 + lc]);
#pragma unroll
            for (int nt = 0; nt < 16; nt++) {
                uint32_t b[2];
                b[0] = __float_as_uint(Vs[(kb + lc) * VLD + nt * 8 + lr]);
                b[1] = __float_as_uint(Vs[(kb + 4 + lc) * VLD + nt * 8 + lr]);
                mma_tf32(oacc[nt], a, b);
            }
        }
        __syncwarp();
    }

    float inv0 = 1.f / l0, inv1 = 1.f / l1;
#pragma unroll
    for (int nt = 0; nt < 16; nt++) {
        int cc = nt * 8 + 2 * lc;
        size_t o0 = (size_t)r0g * (NHQ * DH) + h * DH + cc;
        size_t o1 = (size_t)r1g * (NHQ * DH) + h * DH + cc;
        *(float2*)&o[o0] = make_float2(oacc[nt][0] * inv0, oacc[nt][1] * inv0);
        *(float2*)&o[o1] = make_float2(oacc[nt][2] * inv1, oacc[nt][3] * inv1);
    }
}

// ---------------- router + MoE routing ----------------
__global__ void k_router(const float* __restrict__ h, const float* __restrict__ w,
                         float* __restrict__ logits, float* __restrict__ out2)
{
    int t = blockIdx.x * 8 + (threadIdx.x >> 5);
    int lane = threadIdx.x & 31;
    const float* xr = h + (size_t)t * HD;
    float acc[NE];
#pragma unroll
    for (int e = 0; e < NE; e++) acc[e] = 0.f;
    for (int hh = lane; hh < HD; hh += 32) {
        float xv = xr[hh];
        const float* wr = w + hh * NE;
#pragma unroll
        for (int e = 0; e < NE; e++) acc[e] += xv * wr[e];
    }
#pragma unroll
    for (int e = 0; e < NE; e++)
#pragma unroll
        for (int o = 16; o; o >>= 1) acc[e] += __shfl_xor_sync(0xffffffffu, acc[e], o);
    if (lane == 0) {
#pragma unroll
        for (int e = 0; e < NE; e++) {
            logits[t * NE + e] = acc[e];
            out2[t * NE + e] = acc[e];
        }
    }
}

__global__ void k_zero_cnt()
{
    if (threadIdx.x < NE) g_cnt[threadIdx.x] = 0;
}

__global__ void k_top2(const float* __restrict__ logits)
{
    int t = blockIdx.x * 256 + threadIdx.x;
    if (t >= TT) return;
    const float* l = logits + t * NE;
    int i0 = 0; float v0 = l[0];
#pragma unroll
    for (int e = 1; e < NE; e++) { float v = l[e]; if (v > v0) { v0 = v; i0 = e; } }
    int i1 = -1; float v1 = -FLT_MAX;
#pragma unroll
    for (int e = 0; e < NE; e++) {
        if (e == i0) continue;
        float v = l[e];
        if (v > v1) { v1 = v; i1 = e; }
    }
    g_sel[t * 2] = i0;
    g_sel[t * 2 + 1] = i1;
    atomicAdd(&g_cnt[i0], 1);
    atomicAdd(&g_cnt[i1], 1);
}

__global__ void k_offsets()
{
    int s = 0;
    for (int e = 0; e < NE; e++) { g_off[e] = s; s += g_cnt[e]; g_fill[e] = 0; }
}

__global__ void k_fill()
{
    int t = blockIdx.x * 256 + threadIdx.x;
    if (t >= TT) return;
#pragma unroll
    for (int j = 0; j < 2; j++) {
        int e = g_sel[t * 2 + j];
        int pos = atomicAdd(&g_fill[e], 1);
        int slot = g_off[e] + pos;
        g_tok[slot] = t;
        g_slot[t * 2 + j] = slot;
    }
}

__global__ void k_final(float* __restrict__ out)
{
    size_t i = (size_t)blockIdx.x * 256 + threadIdx.x;
    int t = (int)(i >> 11);
    int c = (int)(i & 2047);
    int s0 = g_slot[t * 2];
    int s1 = g_slot[t * 2 + 1];
    out[i] = g_h[i] + g_down[(size_t)s0 * HD + c] + g_down[(size_t)s1 * HD + c];
}

// ---------------- launch ----------------
extern "C" void kernel_launch(void* const* d_in, const int* in_sizes, int n_in,
                              void* d_out, int out_size)
{
    const float* hidden   = (const float*)d_in[0];
    const float* wq       = (const float*)d_in[1];
    const float* wk       = (const float*)d_in[2];
    const float* wv       = (const float*)d_in[3];
    const float* wo       = (const float*)d_in[4];
    const float* q_scale  = (const float*)d_in[5];
    const float* k_scale  = (const float*)d_in[6];
    const float* router_w = (const float*)d_in[7];
    const float* w_up     = (const float*)d_in[8];
    const float* b_up     = (const float*)d_in[9];
    const float* w_down   = (const float*)d_in[10];
    const float* b_down   = (const float*)d_in[11];
    float* out = (float*)d_out;

    float *qb, *kb, *vb, *ab, *hb, *lb;
    cudaGetSymbolAddress((void**)&qb, g_q);
    cudaGetSymbolAddress((void**)&kb, g_k);
    cudaGetSymbolAddress((void**)&vb, g_v);
    cudaGetSymbolAddress((void**)&ab, g_attn);
    cudaGetSymbolAddress((void**)&hb, g_h);
    cudaGetSymbolAddress((void**)&lb, g_logits);

    cudaFuncSetAttribute(k_qkv, cudaFuncAttributeMaxDynamicSharedMemorySize, GEMM_SMEM);
    cudaFuncSetAttribute(k_gemm_resid, cudaFuncAttributeMaxDynamicSharedMemorySize, GEMM_SMEM);
    cudaFuncSetAttribute(k_moe_up, cudaFuncAttributeMaxDynamicSharedMemorySize, GEMM_SMEM);
    cudaFuncSetAttribute(k_moe_down, cudaFuncAttributeMaxDynamicSharedMemorySize, GEMM_SMEM);

    // fused QKV projection
    k_qkv<<<dim3(24, 16), 256, GEMM_SMEM>>>(hidden, wq, wk, wv, qb, kb, vb);

    k_norm_rope<<<dim3(TT, NHQ + NHKV), 128>>>(qb, kb, q_scale, k_scale);

    const int attn_smem = (128 * QLD + 64 * KLD + 64 * VLD + 128 * PLD) * 4;
    cudaFuncSetAttribute(k_attn_tc, cudaFuncAttributeMaxDynamicSharedMemorySize, attn_smem);
    k_attn_tc<<<dim3(16, NHQ), 256, attn_smem>>>(qb, kb, vb, ab);

    k_gemm_resid<<<dim3(16, 16), 256, GEMM_SMEM>>>(ab, wo, hb, hidden, TT, HD, HD);

    k_router<<<TT / 8, 256>>>(hb, router_w, lb, out + (size_t)TT * HD);

    k_zero_cnt<<<1, 32>>>();
    k_top2<<<TT / 256, 256>>>(lb);
    k_offsets<<<1, 1>>>();
    k_fill<<<TT / 256, 256>>>();

    k_moe_up<<<dim3(NI / 128, 16, NE), 256, GEMM_SMEM>>>(hb, w_up, b_up);
    k_moe_down<<<dim3(HD / 128, 16, NE), 256, GEMM_SMEM>>>(w_down, b_down);

    k_final<<<(TT * HD) / 256, 256>>>(out);
}

// round 5
// speedup vs baseline: 5.7113x; 1.0743x over previous
#include <cuda_runtime.h>
#include <math.h>
#include <float.h>
#include <stdint.h>

// ---------------- problem constants ----------------
#define TT   2048
#define HD   2048
#define NHQ  16
#define NHKV 4
#define DH   128
#define NE   16
#define NI   768

// ---------------- device scratch ----------------
__device__ float g_q[TT * NHQ * DH];
__device__ float g_k[TT * NHKV * DH];
__device__ float g_v[TT * NHKV * DH];
__device__ float g_attn[TT * NHQ * DH];
__device__ float g_h[TT * HD];
__device__ float g_logits[TT * NE];
__device__ int   g_sel[TT * 2];
__device__ int   g_cnt[NE];
__device__ int   g_off[NE];
__device__ int   g_fill[NE];
__device__ int   g_tok[TT * 2];
__device__ int   g_slot[TT * 2];
__device__ float g_up[TT * 2 * NI];
__device__ float g_down[TT * 2 * HD];

// ---------------- tf32 / cp.async helpers ----------------
__device__ __forceinline__ uint32_t f2tf32(float x) {
    uint32_t r;
    asm("cvt.rna.tf32.f32 %0, %1;" : "=r"(r) : "f"(x));
    return r;
}
__device__ __forceinline__ float tf(float x) { return __uint_as_float(f2tf32(x)); }

__device__ __forceinline__ void mma_tf32(float c[4], const uint32_t a[4], const uint32_t b[2]) {
    asm volatile(
        "mma.sync.aligned.m16n8k8.row.col.f32.tf32.tf32.f32 "
        "{%0,%1,%2,%3}, {%4,%5,%6,%7}, {%8,%9}, {%0,%1,%2,%3};"
        : "+f"(c[0]), "+f"(c[1]), "+f"(c[2]), "+f"(c[3])
        : "r"(a[0]), "r"(a[1]), "r"(a[2]), "r"(a[3]), "r"(b[0]), "r"(b[1]));
}

__device__ __forceinline__ void cpa16(uint32_t dst, const void* src, bool pred) {
    int sz = pred ? 16 : 0;
    asm volatile("cp.async.cg.shared.global [%0], [%1], 16, %2;\n"
                 :: "r"(dst), "l"(src), "r"(sz));
}
__device__ __forceinline__ void cp_commit() {
    asm volatile("cp.async.commit_group;\n" ::: "memory");
}
__device__ __forceinline__ void cp_wait0() {
    asm volatile("cp.async.wait_group 0;\n" ::: "memory");
}

// ---------------- tf32 tensor-core GEMM core (cp.async double-buffered) ----------------
#define AST 36
#define BST 136
#define ASZ (128 * AST)
#define BSZ (32 * BST)
#define GEMM_SMEM ((2 * ASZ + 2 * BSZ) * 4)

template<bool GATHER, bool BIAS, bool SILU, bool RESID>
__device__ __forceinline__ void gemm_tc(
    const float* __restrict__ A, int lda, const int* __restrict__ gidx,
    const float* __restrict__ B, int ldb,
    float* __restrict__ C, int ldc,
    const float* __restrict__ bias,
    const float* __restrict__ resid,
    int M, int K, int bm, int bn)
{
    extern __shared__ float smem[];
    float* As = smem;               // [2][128][AST]
    float* Bs = smem + 2 * ASZ;     // [2][32][BST]

    const int tid  = threadIdx.x;
    const int wid  = tid >> 5;
    const int lane = tid & 31;
    const int warp_m = (wid >> 1) * 32;
    const int warp_n = (wid & 1) * 64;
    const int lr = lane >> 2;
    const int lc = lane & 3;

    float c[2][8][4];
#pragma unroll
    for (int mt = 0; mt < 2; mt++)
#pragma unroll
        for (int nt = 0; nt < 8; nt++)
#pragma unroll
            for (int i = 0; i < 4; i++) c[mt][nt][i] = 0.f;

    const int am  = tid >> 3;
    const int ak4 = (tid & 7) * 4;
    const int bk  = tid >> 5;
    const int bn4 = (tid & 31) * 4;

    const float* asrc[4];
    bool aok[4];
#pragma unroll
    for (int i = 0; i < 4; i++) {
        int grow = bm + am + 32 * i;
        aok[i] = (grow < M);
        const float* p = A;
        if (aok[i]) p = A + (size_t)(GATHER ? gidx[grow] : grow) * lda;
        asrc[i] = p + ak4;
    }
    const float* bsrc[4];
#pragma unroll
    for (int i = 0; i < 4; i++)
        bsrc[i] = B + (size_t)(bk + 8 * i) * ldb + bn + bn4;

    uint32_t sa = (uint32_t)__cvta_generic_to_shared(As);
    uint32_t sb = (uint32_t)__cvta_generic_to_shared(Bs);
    uint32_t adst[4], bdst[4];
#pragma unroll
    for (int i = 0; i < 4; i++) {
        adst[i] = sa + ((am + 32 * i) * AST + ak4) * 4;
        bdst[i] = sb + ((bk + 8 * i) * BST + bn4) * 4;
    }

    // stage 0
#pragma unroll
    for (int i = 0; i < 4; i++) cpa16(adst[i], asrc[i], aok[i]);
#pragma unroll
    for (int i = 0; i < 4; i++) cpa16(bdst[i], bsrc[i], true);
    cp_commit();

    const int nch = K >> 5;
    for (int ch = 0; ch < nch; ch++) {
        cp_wait0();
        __syncthreads();

        if (ch + 1 < nch) {
            const int koff = (ch + 1) * 32;
            const uint32_t ao = ((ch + 1) & 1) ? ASZ * 4 : 0;
            const uint32_t bo = ((ch + 1) & 1) ? BSZ * 4 : 0;
#pragma unroll
            for (int i = 0; i < 4; i++) cpa16(adst[i] + ao, asrc[i] + koff, aok[i]);
#pragma unroll
            for (int i = 0; i < 4; i++) cpa16(bdst[i] + bo, bsrc[i] + (size_t)koff * ldb, true);
            cp_commit();
        }

        const float* Ac = As + (ch & 1) * ASZ;
        const float* Bc = Bs + (ch & 1) * BSZ;

        // software-pipelined fragment loads: a-frags double buffered over ks
        uint32_t afr[2][2][4];
#pragma unroll
        for (int mt = 0; mt < 2; mt++) {
            int r = warp_m + mt * 16 + lr;
            afr[0][mt][0] = __float_as_uint(Ac[r * AST + lc]);
            afr[0][mt][1] = __float_as_uint(Ac[(r + 8) * AST + lc]);
            afr[0][mt][2] = __float_as_uint(Ac[r * AST + 4 + lc]);
            afr[0][mt][3] = __float_as_uint(Ac[(r + 8) * AST + 4 + lc]);
        }

#pragma unroll
        for (int ks = 0; ks < 4; ks++) {
            const int cur = ks & 1;
            const int nxt = cur ^ 1;
            if (ks < 3) {
                const int kb2 = (ks + 1) * 8;
#pragma unroll
                for (int mt = 0; mt < 2; mt++) {
                    int r = warp_m + mt * 16 + lr;
                    afr[nxt][mt][0] = __float_as_uint(Ac[r * AST + kb2 + lc]);
                    afr[nxt][mt][1] = __float_as_uint(Ac[(r + 8) * AST + kb2 + lc]);
                    afr[nxt][mt][2] = __float_as_uint(Ac[r * AST + kb2 + 4 + lc]);
                    afr[nxt][mt][3] = __float_as_uint(Ac[(r + 8) * AST + kb2 + 4 + lc]);
                }
            }
            const int kb = ks * 8;
            uint32_t b[8][2];
#pragma unroll
            for (int nt = 0; nt < 8; nt++) {
                int col = warp_n + nt * 8 + lr;
                b[nt][0] = __float_as_uint(Bc[(kb + lc) * BST + col]);
                b[nt][1] = __float_as_uint(Bc[(kb + 4 + lc) * BST + col]);
            }
#pragma unroll
            for (int mt = 0; mt < 2; mt++)
#pragma unroll
                for (int nt = 0; nt < 8; nt++)
                    mma_tf32(c[mt][nt], afr[cur][mt], b[nt]);
        }
    }

#pragma unroll
    for (int mt = 0; mt < 2; mt++) {
#pragma unroll
        for (int hh = 0; hh < 2; hh++) {
            int row = bm + warp_m + mt * 16 + hh * 8 + lr;
            if (row >= M) continue;
#pragma unroll
            for (int nt = 0; nt < 8; nt++) {
                int col = bn + warp_n + nt * 8 + 2 * lc;
                float v0 = c[mt][nt][2 * hh + 0];
                float v1 = c[mt][nt][2 * hh + 1];
                if (BIAS) { v0 += bias[col]; v1 += bias[col + 1]; }
                if (SILU) {
                    v0 = v0 / (1.f + expf(-v0));
                    v1 = v1 / (1.f + expf(-v1));
                }
                if (RESID) {
                    v0 += resid[(size_t)row * ldc + col];
                    v1 += resid[(size_t)row * ldc + col + 1];
                }
                *(float2*)&C[(size_t)row * ldc + col] = make_float2(v0, v1);
            }
        }
    }
}

// fused Q/K/V projection: grid (24, 16)
__global__ __launch_bounds__(256, 2)
void k_qkv(const float* __restrict__ x,
           const float* __restrict__ wq, const float* __restrict__ wk,
           const float* __restrict__ wv,
           float* __restrict__ q, float* __restrict__ k, float* __restrict__ v)
{
    const int bx = blockIdx.x;
    const int bm = blockIdx.y * 128;
    if (bx < 16)
        gemm_tc<false, false, false, false>(x, HD, nullptr, wq, NHQ * DH, q, NHQ * DH,
                                            nullptr, nullptr, TT, HD, bm, bx * 128);
    else if (bx < 20)
        gemm_tc<false, false, false, false>(x, HD, nullptr, wk, NHKV * DH, k, NHKV * DH,
                                            nullptr, nullptr, TT, HD, bm, (bx - 16) * 128);
    else
        gemm_tc<false, false, false, false>(x, HD, nullptr, wv, NHKV * DH, v, NHKV * DH,
                                            nullptr, nullptr, TT, HD, bm, (bx - 20) * 128);
}

__global__ __launch_bounds__(256, 2)
void k_gemm_resid(const float* __restrict__ A, const float* __restrict__ B,
                  float* __restrict__ C, const float* __restrict__ resid,
                  int M, int N, int K)
{
    gemm_tc<false, false, false, true>(A, K, nullptr, B, N, C, N,
                                       nullptr, resid, M, K,
                                       blockIdx.y * 128, blockIdx.x * 128);
}

__global__ __launch_bounds__(256, 2)
void k_moe_up(const float* __restrict__ h, const float* __restrict__ w_up,
              const float* __restrict__ b_up)
{
    int e = blockIdx.z;
    int cnt = g_cnt[e];
    int off = g_off[e];
    int bm = blockIdx.y * 128;
    if (bm >= cnt) return;
    gemm_tc<true, true, true, false>(
        h, HD, g_tok + off,
        w_up + (size_t)e * HD * NI, NI,
        g_up + (size_t)off * NI, NI,
        b_up + (size_t)e * NI, nullptr,
        cnt, HD, bm, blockIdx.x * 128);
}

__global__ __launch_bounds__(256, 2)
void k_moe_down(const float* __restrict__ w_down, const float* __restrict__ b_down)
{
    int e = blockIdx.z;
    int cnt = g_cnt[e];
    int off = g_off[e];
    int bm = blockIdx.y * 128;
    if (bm >= cnt) return;
    gemm_tc<false, true, false, false>(
        g_up + (size_t)off * NI, NI, nullptr,
        w_down + (size_t)e * NI * HD, HD,
        g_down + (size_t)off * HD, HD,
        b_down + (size_t)e * HD, nullptr,
        cnt, NI, bm, blockIdx.x * 128);
}

// ---------------- RMSNorm + RoPE ----------------
__global__ void k_norm_rope(float* __restrict__ q, float* __restrict__ k,
                            const float* __restrict__ qs, const float* __restrict__ ks)
{
    int t = blockIdx.x;
    int head = blockIdx.y;
    float* base;
    const float* scale;
    if (head < NHQ) { base = q + ((size_t)t * NHQ + head) * DH; scale = qs; }
    else            { base = k + ((size_t)t * NHKV + (head - NHQ)) * DH; scale = ks; }

    int d = threadIdx.x;
    float x = base[d];
    float ss = x * x;
#pragma unroll
    for (int o = 16; o; o >>= 1) ss += __shfl_xor_sync(0xffffffffu, ss, o);
    __shared__ float wsum[4];
    if ((d & 31) == 0) wsum[d >> 5] = ss;
    __syncthreads();
    float var = (wsum[0] + wsum[1] + wsum[2] + wsum[3]) * (1.f / 128.f);
    float inv = rsqrtf(var + 1e-6f);
    float xn = x * inv * scale[d];

    __shared__ float sh[128];
    sh[d] = xn;
    __syncthreads();

    int i = d & 63;
    float inv_freq = 1.f / powf(10000.f, (float)i / 64.f);
    float ang = (float)t * inv_freq;
    float c = cosf(ang), s = sinf(ang);
    float rot = (d < 64) ? -sh[d + 64] : sh[d - 64];
    base[d] = xn * c + rot * s;
}

// ---------------- tf32 tensor-core flash attention (register-prefetched K/V) ----------------
#define QLD 132
#define KLD 132
#define VLD 136
#define PLD 68

__global__ __launch_bounds__(256)
void k_attn_tc(const float* __restrict__ q, const float* __restrict__ k,
               const float* __restrict__ v, float* __restrict__ o)
{
    extern __shared__ float sm[];
    float* Qs = sm;                       // [128][132]
    float* Ks = Qs + 128 * QLD;           // [64][132]
    float* Vs = Ks + 64 * KLD;            // [64][136]
    float* Ps = Vs + 64 * VLD;            // [128][68]

    const int h  = blockIdx.y;
    const int kh = h >> 2;
    const int qt = gridDim.x - 1 - blockIdx.x;
    const int q0 = qt * 128;
    const int tid = threadIdx.x;
    const int wid = tid >> 5;
    const int lane = tid & 31;
    const int lr = lane >> 2;
    const int lc = lane & 3;
    const int wm = wid * 16;
    const float scale = 0.08838834764831845f;

    // per-thread K/V staging coordinates (8 chunks each)
    int ldr[8], ldd[8];
#pragma unroll
    for (int i = 0; i < 8; i++) {
        int idx = tid + 256 * i;
        ldr[i] = idx >> 5;
        ldd[i] = (idx & 31) << 2;
    }

    for (int idx = tid; idx < 4096; idx += 256) {
        int r = idx >> 5;
        int d4 = (idx & 31) << 2;
        float4 val = *(const float4*)(q + (size_t)(q0 + r) * (NHQ * DH) + h * DH + d4);
        float4 w;
        w.x = tf(val.x); w.y = tf(val.y); w.z = tf(val.z); w.w = tf(val.w);
        *(float4*)&Qs[r * QLD + d4] = w;
    }

    float oacc[16][4];
#pragma unroll
    for (int nt = 0; nt < 16; nt++)
#pragma unroll
        for (int i = 0; i < 4; i++) oacc[nt][i] = 0.f;
    float m0 = -FLT_MAX, m1 = -FLT_MAX, l0 = 0.f, l1 = 0.f;

    const int r0g = q0 + wm + lr;
    const int r1g = r0g + 8;
    const int ntiles = 2 * qt + 2;

    // prefetch tile 0 K/V into registers
    float4 kreg[8], vreg[8];
#pragma unroll
    for (int i = 0; i < 8; i++) {
        kreg[i] = *(const float4*)(k + (size_t)ldr[i] * (NHKV * DH) + kh * DH + ldd[i]);
        vreg[i] = *(const float4*)(v + (size_t)ldr[i] * (NHKV * DH) + kh * DH + ldd[i]);
    }

    for (int tile = 0; tile < ntiles; ++tile) {
        const int k0 = tile * 64;
        __syncthreads();
        // commit prefetched tile to smem (tf32)
#pragma unroll
        for (int i = 0; i < 8; i++) {
            float4 val = kreg[i];
            float4 w;
            w.x = tf(val.x); w.y = tf(val.y); w.z = tf(val.z); w.w = tf(val.w);
            *(float4*)&Ks[ldr[i] * KLD + ldd[i]] = w;
            val = vreg[i];
            w.x = tf(val.x); w.y = tf(val.y); w.z = tf(val.z); w.w = tf(val.w);
            *(float4*)&Vs[ldr[i] * VLD + ldd[i]] = w;
        }
        __syncthreads();

        // prefetch next tile while computing this one
        if (tile + 1 < ntiles) {
            const int kn = (tile + 1) * 64;
#pragma unroll
            for (int i = 0; i < 8; i++) {
                kreg[i] = *(const float4*)(k + (size_t)(kn + ldr[i]) * (NHKV * DH) + kh * DH + ldd[i]);
                vreg[i] = *(const float4*)(v + (size_t)(kn + ldr[i]) * (NHKV * DH) + kh * DH + ldd[i]);
            }
        }

        float sa[8][4];
#pragma unroll
        for (int nt = 0; nt < 8; nt++)
#pragma unroll
            for (int i = 0; i < 4; i++) sa[nt][i] = 0.f;

#pragma unroll
        for (int dk = 0; dk < 16; ++dk) {
            const int kb = dk * 8;
            uint32_t a[4];
            a[0] = __float_as_uint(Qs[(wm + lr) * QLD + kb + lc]);
            a[1] = __float_as_uint(Qs[(wm + lr + 8) * QLD + kb + lc]);
            a[2] = __float_as_uint(Qs[(wm + lr) * QLD + kb + 4 + lc]);
            a[3] = __float_as_uint(Qs[(wm + lr + 8) * QLD + kb + 4 + lc]);
#pragma unroll
            for (int nt = 0; nt < 8; nt++) {
                uint32_t b[2];
                b[0] = __float_as_uint(Ks[(nt * 8 + lr) * KLD + kb + lc]);
                b[1] = __float_as_uint(Ks[(nt * 8 + lr) * KLD + kb + 4 + lc]);
                mma_tf32(sa[nt], a, b);
            }
        }

        float mx0 = -FLT_MAX, mx1 = -FLT_MAX;
#pragma unroll
        for (int nt = 0; nt < 8; nt++) {
            int cc = k0 + nt * 8 + 2 * lc;
            sa[nt][0] = (cc     <= r0g) ? sa[nt][0] * scale : -FLT_MAX;
            sa[nt][1] = (cc + 1 <= r0g) ? sa[nt][1] * scale : -FLT_MAX;
            sa[nt][2] = (cc     <= r1g) ? sa[nt][2] * scale : -FLT_MAX;
            sa[nt][3] = (cc + 1 <= r1g) ? sa[nt][3] * scale : -FLT_MAX;
            mx0 = fmaxf(mx0, fmaxf(sa[nt][0], sa[nt][1]));
            mx1 = fmaxf(mx1, fmaxf(sa[nt][2], sa[nt][3]));
        }
        mx0 = fmaxf(mx0, __shfl_xor_sync(0xffffffffu, mx0, 1));
        mx0 = fmaxf(mx0, __shfl_xor_sync(0xffffffffu, mx0, 2));
        mx1 = fmaxf(mx1, __shfl_xor_sync(0xffffffffu, mx1, 1));
        mx1 = fmaxf(mx1, __shfl_xor_sync(0xffffffffu, mx1, 2));

        float mn0 = fmaxf(m0, mx0), mn1 = fmaxf(m1, mx1);
        float al0 = expf(m0 - mn0), al1 = expf(m1 - mn1);

        float ps0 = 0.f, ps1 = 0.f;
#pragma unroll
        for (int nt = 0; nt < 8; nt++) {
            sa[nt][0] = expf(sa[nt][0] - mn0);
            sa[nt][1] = expf(sa[nt][1] - mn0);
            sa[nt][2] = expf(sa[nt][2] - mn1);
            sa[nt][3] = expf(sa[nt][3] - mn1);
            ps0 += sa[nt][0] + sa[nt][1];
            ps1 += sa[nt][2] + sa[nt][3];
        }
        ps0 += __shfl_xor_sync(0xffffffffu, ps0, 1);
        ps0 += __shfl_xor_sync(0xffffffffu, ps0, 2);
        ps1 += __shfl_xor_sync(0xffffffffu, ps1, 1);
        ps1 += __shfl_xor_sync(0xffffffffu, ps1, 2);

        l0 = l0 * al0 + ps0;
        l1 = l1 * al1 + ps1;
        m0 = mn0; m1 = mn1;

#pragma unroll
        for (int nt = 0; nt < 16; nt++) {
            oacc[nt][0] *= al0; oacc[nt][1] *= al0;
            oacc[nt][2] *= al1; oacc[nt][3] *= al1;
        }

#pragma unroll
        for (int nt = 0; nt < 8; nt++) {
            int cc = nt * 8 + 2 * lc;
            *(float2*)&Ps[(wm + lr) * PLD + cc]     = make_float2(tf(sa[nt][0]), tf(sa[nt][1]));
            *(float2*)&Ps[(wm + lr + 8) * PLD + cc] = make_float2(tf(sa[nt][2]), tf(sa[nt][3]));
        }
        __syncwarp();

#pragma unroll
        for (int kc = 0; kc < 8; ++kc) {
            const int kb = kc * 8;
            uint32_t a[4];
            a[0] = __float_as_uint(Ps[(wm + lr) * PLD + kb + lc]);
            a[1] = __float_as_uint(Ps[(wm + lr + 8) * PLD + kb + lc]);
            a[2] = __float_as_uint(Ps[(wm + lr) * PLD + kb + 4 + lc]);
            a[3] = __float_as_uint(Ps[(wm + lr + 8) * PLD + kb + 4 + lc]);
#pragma unroll
            for (int nt = 0; nt < 16; nt++) {
                uint32_t b[2];
                b[0] = __float_as_uint(Vs[(kb + lc) * VLD + nt * 8 + lr]);
                b[1] = __float_as_uint(Vs[(kb + 4 + lc) * VLD + nt * 8 + lr]);
                mma_tf32(oacc[nt], a, b);
            }
        }
        __syncwarp();
    }

    float inv0 = 1.f / l0, inv1 = 1.f / l1;
#pragma unroll
    for (int nt = 0; nt < 16; nt++) {
        int cc = nt * 8 + 2 * lc;
        size_t o0 = (size_t)r0g * (NHQ * DH) + h * DH + cc;
        size_t o1 = (size_t)r1g * (NHQ * DH) + h * DH + cc;
        *(float2*)&o[o0] = make_float2(oacc[nt][0] * inv0, oacc[nt][1] * inv0);
        *(float2*)&o[o1] = make_float2(oacc[nt][2] * inv1, oacc[nt][3] * inv1);
    }
}

// ---------------- router + MoE routing ----------------
__global__ void k_router(const float* __restrict__ h, const float* __restrict__ w,
                         float* __restrict__ logits, float* __restrict__ out2)
{
    int t = blockIdx.x * 8 + (threadIdx.x >> 5);
    int lane = threadIdx.x & 31;
    const float* xr = h + (size_t)t * HD;
    float acc[NE];
#pragma unroll
    for (int e = 0; e < NE; e++) acc[e] = 0.f;
    for (int hh = lane; hh < HD; hh += 32) {
        float xv = xr[hh];
        const float* wr = w + hh * NE;
#pragma unroll
        for (int e = 0; e < NE; e++) acc[e] += xv * wr[e];
    }
#pragma unroll
    for (int e = 0; e < NE; e++)
#pragma unroll
        for (int o = 16; o; o >>= 1) acc[e] += __shfl_xor_sync(0xffffffffu, acc[e], o);
    if (lane == 0) {
#pragma unroll
        for (int e = 0; e < NE; e++) {
            logits[t * NE + e] = acc[e];
            out2[t * NE + e] = acc[e];
        }
    }
}

__global__ void k_zero_cnt()
{
    if (threadIdx.x < NE) g_cnt[threadIdx.x] = 0;
}

__global__ void k_top2(const float* __restrict__ logits)
{
    int t = blockIdx.x * 256 + threadIdx.x;
    if (t >= TT) return;
    const float* l = logits + t * NE;
    int i0 = 0; float v0 = l[0];
#pragma unroll
    for (int e = 1; e < NE; e++) { float v = l[e]; if (v > v0) { v0 = v; i0 = e; } }
    int i1 = -1; float v1 = -FLT_MAX;
#pragma unroll
    for (int e = 0; e < NE; e++) {
        if (e == i0) continue;
        float v = l[e];
        if (v > v1) { v1 = v; i1 = e; }
    }
    g_sel[t * 2] = i0;
    g_sel[t * 2 + 1] = i1;
    atomicAdd(&g_cnt[i0], 1);
    atomicAdd(&g_cnt[i1], 1);
}

__global__ void k_offsets()
{
    int s = 0;
    for (int e = 0; e < NE; e++) { g_off[e] = s; s += g_cnt[e]; g_fill[e] = 0; }
}

__global__ void k_fill()
{
    int t = blockIdx.x * 256 + threadIdx.x;
    if (t >= TT) return;
#pragma unroll
    for (int j = 0; j < 2; j++) {
        int e = g_sel[t * 2 + j];
        int pos = atomicAdd(&g_fill[e], 1);
        int slot = g_off[e] + pos;
        g_tok[slot] = t;
        g_slot[t * 2 + j] = slot;
    }
}

__global__ void k_final(float* __restrict__ out)
{
    size_t i = (size_t)blockIdx.x * 256 + threadIdx.x;
    int t = (int)(i >> 11);
    int c = (int)(i & 2047);
    int s0 = g_slot[t * 2];
    int s1 = g_slot[t * 2 + 1];
    out[i] = g_h[i] + g_down[(size_t)s0 * HD + c] + g_down[(size_t)s1 * HD + c];
}

// ---------------- launch ----------------
extern "C" void kernel_launch(void* const* d_in, const int* in_sizes, int n_in,
                              void* d_out, int out_size)
{
    const float* hidden   = (const float*)d_in[0];
    const float* wq       = (const float*)d_in[1];
    const float* wk       = (const float*)d_in[2];
    const float* wv       = (const float*)d_in[3];
    const float* wo       = (const float*)d_in[4];
    const float* q_scale  = (const float*)d_in[5];
    const float* k_scale  = (const float*)d_in[6];
    const float* router_w = (const float*)d_in[7];
    const float* w_up     = (const float*)d_in[8];
    const float* b_up     = (const float*)d_in[9];
    const float* w_down   = (const float*)d_in[10];
    const float* b_down   = (const float*)d_in[11];
    float* out = (float*)d_out;

    float *qb, *kb, *vb, *ab, *hb, *lb;
    cudaGetSymbolAddress((void**)&qb, g_q);
    cudaGetSymbolAddress((void**)&kb, g_k);
    cudaGetSymbolAddress((void**)&vb, g_v);
    cudaGetSymbolAddress((void**)&ab, g_attn);
    cudaGetSymbolAddress((void**)&hb, g_h);
    cudaGetSymbolAddress((void**)&lb, g_logits);

    cudaFuncSetAttribute(k_qkv, cudaFuncAttributeMaxDynamicSharedMemorySize, GEMM_SMEM);
    cudaFuncSetAttribute(k_gemm_resid, cudaFuncAttributeMaxDynamicSharedMemorySize, GEMM_SMEM);
    cudaFuncSetAttribute(k_moe_up, cudaFuncAttributeMaxDynamicSharedMemorySize, GEMM_SMEM);
    cudaFuncSetAttribute(k_moe_down, cudaFuncAttributeMaxDynamicSharedMemorySize, GEMM_SMEM);

    k_qkv<<<dim3(24, 16), 256, GEMM_SMEM>>>(hidden, wq, wk, wv, qb, kb, vb);

    k_norm_rope<<<dim3(TT, NHQ + NHKV), 128>>>(qb, kb, q_scale, k_scale);

    const int attn_smem = (128 * QLD + 64 * KLD + 64 * VLD + 128 * PLD) * 4;
    cudaFuncSetAttribute(k_attn_tc, cudaFuncAttributeMaxDynamicSharedMemorySize, attn_smem);
    k_attn_tc<<<dim3(16, NHQ), 256, attn_smem>>>(qb, kb, vb, ab);

    k_gemm_resid<<<dim3(16, 16), 256, GEMM_SMEM>>>(ab, wo, hb, hidden, TT, HD, HD);

    k_router<<<TT / 8, 256>>>(hb, router_w, lb, out + (size_t)TT * HD);

    k_zero_cnt<<<1, 32>>>();
    k_top2<<<TT / 256, 256>>>(lb);
    k_offsets<<<1, 1>>>();
    k_fill<<<TT / 256, 256>>>();

    k_moe_up<<<dim3(NI / 128, 16, NE), 256, GEMM_SMEM>>>(hb, w_up, b_up);
    k_moe_down<<<dim3(HD / 128, 16, NE), 256, GEMM_SMEM>>>(w_down, b_down);

    k_final<<<(TT * HD) / 256, 256>>>(out);
}